// round 1
// baseline (speedup 1.0000x reference)
#include <cuda_runtime.h>

#define N_NODES 200000
#define N_EDGES 6400000
#define IN_DIM  128
#define H1      256
#define HID     16
#define NEG     0.01f

// ---------------- scratch (device globals; no runtime allocation) ----------
__device__ __align__(16) float g_dinv[N_NODES];
__device__ __align__(16) float g_h  [N_NODES * HID];
__device__ __align__(16) float g_t  [N_NODES * HID];
__device__ __align__(16) float g_acc[N_NODES * HID];

__device__ __forceinline__ float lrelu(float v) { return v >= 0.f ? v : NEG * v; }

__device__ __forceinline__ void red_add_v4(float* p, float4 v) {
    asm volatile("red.global.add.v4.f32 [%0], {%1,%2,%3,%4};"
                 :: "l"(p), "f"(v.x), "f"(v.y), "f"(v.z), "f"(v.w) : "memory");
}

// ---------------- degree / dinv --------------------------------------------
__global__ __launch_bounds__(256) void k_zero() {
    int i = blockIdx.x * 256 + threadIdx.x;
    if (i < N_NODES) g_dinv[i] = 0.f;
}

__global__ __launch_bounds__(256) void k_deg(const int* __restrict__ ei) {
    int e = blockIdx.x * 256 + threadIdx.x;          // grid covers E exactly
    int dst = ei[N_EDGES + e];
    atomicAdd(&g_dinv[dst], 1.0f);
}

__global__ __launch_bounds__(256) void k_dinv() {
    int i = blockIdx.x * 256 + threadIdx.x;
    if (i < N_NODES) g_dinv[i] = rsqrtf(g_dinv[i] + 1.0f);   // +1 self loop
}

// ---------------- fused MLP: h = lrelu(lrelu(x@W1+b1)@W2+b2) ---------------
// 32 rows per block, 256 threads.
//   s_a: x transposed [128][32] (16KB), later W2 [256][16] (16KB)
//   s_b: W1 k-chunk  [32][256]  (32KB), later hidden transposed+swizzled (32KB)
__global__ __launch_bounds__(256) void k_mlp(const float* __restrict__ x,
                                             const float* __restrict__ W1,
                                             const float* __restrict__ b1,
                                             const float* __restrict__ W2,
                                             const float* __restrict__ b2) {
    __shared__ float s_a[4096];
    __shared__ float s_b[8192];
    const int tid = threadIdx.x;
    const int rowbase = blockIdx.x * 32;

    // ---- load x tile transposed: s_a[k*32 + r] = x[rowbase+r][k] ----
    {
        int row = tid & 31, kq = tid >> 5;   // kq in 0..7
        const float4* xr = (const float4*)(x + (size_t)(rowbase + row) * IN_DIM);
        #pragma unroll
        for (int it = 0; it < 4; ++it) {
            int k4 = kq + it * 8;            // float4 index 0..31
            float4 v = xr[k4];
            s_a[(k4 * 4 + 0) * 32 + row] = v.x;
            s_a[(k4 * 4 + 1) * 32 + row] = v.y;
            s_a[(k4 * 4 + 2) * 32 + row] = v.z;
            s_a[(k4 * 4 + 3) * 32 + row] = v.w;
        }
    }

    const int r0 = (tid >> 6) * 8;    // 4 row groups of 8
    const int c0 = (tid & 63) * 4;    // 64 col groups of 4

    float acc[8][4];
    #pragma unroll
    for (int i = 0; i < 8; ++i)
        #pragma unroll
        for (int j = 0; j < 4; ++j) acc[i][j] = 0.f;

    // ---- GEMM1: [32,128] @ [128,256], W1 streamed in 4 K-chunks of 32 ----
    for (int kc = 0; kc < 4; ++kc) {
        __syncthreads();
        const float4* src = (const float4*)(W1 + (size_t)kc * 32 * 256);
        float4* dst = (float4*)s_b;
        #pragma unroll
        for (int it = 0; it < 8; ++it) dst[tid + it * 256] = src[tid + it * 256];
        __syncthreads();
        #pragma unroll
        for (int kk = 0; kk < 32; ++kk) {
            float4 w = *(const float4*)&s_b[kk * 256 + c0];
            const float* xp = &s_a[(kc * 32 + kk) * 32 + r0];
            float4 xa = *(const float4*)xp;
            float4 xb = *(const float4*)(xp + 4);
            float xv[8] = {xa.x, xa.y, xa.z, xa.w, xb.x, xb.y, xb.z, xb.w};
            #pragma unroll
            for (int i = 0; i < 8; ++i) {
                acc[i][0] += xv[i] * w.x;
                acc[i][1] += xv[i] * w.y;
                acc[i][2] += xv[i] * w.z;
                acc[i][3] += xv[i] * w.w;
            }
        }
    }

    float4 bb = *(const float4*)(b1 + c0);
    __syncthreads();   // everyone done reading s_a / s_b

    // ---- bias + leaky, store hidden transposed & swizzled into s_b ----
    {
        float bj[4] = {bb.x, bb.y, bb.z, bb.w};
        #pragma unroll
        for (int i = 0; i < 8; ++i) {
            int r = r0 + i;
            #pragma unroll
            for (int j = 0; j < 4; ++j) {
                int c = c0 + j;
                s_b[c * 32 + ((r + c) & 31)] = lrelu(acc[i][j] + bj[j]);
            }
        }
    }
    // ---- load W2 [256][16] into s_a ----
    {
        const float4* w2v = (const float4*)W2;
        float4* da = (float4*)s_a;
        #pragma unroll
        for (int it = 0; it < 4; ++it) da[tid + it * 256] = w2v[tid + it * 256];
    }
    __syncthreads();

    // ---- GEMM2: [32,256] @ [256,16] + bias + leaky -> g_h ----
    const int row = tid >> 3;
    const int jp  = tid & 7;
    float a0 = 0.f, a1 = 0.f;
    #pragma unroll 8
    for (int k = 0; k < 256; ++k) {
        float hv = s_b[k * 32 + ((row + k) & 31)];
        a0 += hv * s_a[k * 16 + jp];
        a1 += hv * s_a[k * 16 + jp + 8];
    }
    a0 = lrelu(a0 + b2[jp]);
    a1 = lrelu(a1 + b2[jp + 8]);
    size_t o = (size_t)(rowbase + row) * 16 + jp;
    g_h[o]     = a0;
    g_h[o + 8] = a1;
}

// ---------------- t = dinv * (h @ W);  acc = t (self-loop seed) ------------
__global__ __launch_bounds__(256) void k_t(const float* __restrict__ W) {
    __shared__ float Ws[256];
    Ws[threadIdx.x] = W[threadIdx.x];
    __syncthreads();
    int i = blockIdx.x * 256 + threadIdx.x;
    if (i >= N_NODES) return;

    const float4* hp = (const float4*)(g_h + (size_t)i * 16);
    float4 h0 = hp[0], h1 = hp[1], h2 = hp[2], h3 = hp[3];
    float hr[16] = {h0.x, h0.y, h0.z, h0.w, h1.x, h1.y, h1.z, h1.w,
                    h2.x, h2.y, h2.z, h2.w, h3.x, h3.y, h3.z, h3.w};
    float acc[16];
    #pragma unroll
    for (int j = 0; j < 16; ++j) acc[j] = 0.f;
    #pragma unroll
    for (int k = 0; k < 16; ++k) {
        float hv = hr[k];
        #pragma unroll
        for (int j = 0; j < 16; ++j) acc[j] += hv * Ws[k * 16 + j];
    }
    float d = g_dinv[i];
    float4* tp = (float4*)(g_t + (size_t)i * 16);
    float4* ap = (float4*)(g_acc + (size_t)i * 16);
    #pragma unroll
    for (int q = 0; q < 4; ++q) {
        float4 v = make_float4(acc[q*4+0]*d, acc[q*4+1]*d, acc[q*4+2]*d, acc[q*4+3]*d);
        tp[q] = v;
        ap[q] = v;
    }
}

// ---------------- edge scatter: acc[dst] += t[src]  (4 threads / edge) -----
__global__ __launch_bounds__(256) void k_scatter(const int* __restrict__ ei) {
    unsigned gt = blockIdx.x * 256u + threadIdx.x;   // grid covers 4*E exactly
    int e = gt >> 2, p = gt & 3;
    int src = ei[e];
    int dst = ei[N_EDGES + e];
    float4 v = *(const float4*)(g_t + (size_t)src * 16 + p * 4);
    red_add_v4(g_acc + (size_t)dst * 16 + p * 4, v);
}

// ---------------- finalize: h = lrelu(dinv*acc + b) ------------------------
__global__ __launch_bounds__(256) void k_fin(const float* __restrict__ b) {
    int idx = blockIdx.x * 256 + threadIdx.x;        // covers N*4 exactly
    int node = idx >> 2, q = idx & 3;
    float d = g_dinv[node];
    float4 a  = *(const float4*)(g_acc + (size_t)idx * 4);
    float4 bv = *(const float4*)(b + q * 4);
    float4 r;
    r.x = lrelu(d * a.x + bv.x);
    r.y = lrelu(d * a.y + bv.y);
    r.z = lrelu(d * a.z + bv.z);
    r.w = lrelu(d * a.w + bv.w);
    *(float4*)(g_h + (size_t)idx * 4) = r;
}

// ---------------- head: out[i] = h[i]·(pw·1) + sum(pb); copy h -------------
__global__ __launch_bounds__(256) void k_out(const float* __restrict__ pw,
                                             const float* __restrict__ pb,
                                             float* __restrict__ out) {
    int i = blockIdx.x * 256 + threadIdx.x;
    if (i >= N_NODES) return;
    float bs = pb[0] + pb[1];
    const float4* hp = (const float4*)(g_h + (size_t)i * 16);
    float4 h0 = hp[0], h1 = hp[1], h2 = hp[2], h3 = hp[3];
    float hr[16] = {h0.x, h0.y, h0.z, h0.w, h1.x, h1.y, h1.z, h1.w,
                    h2.x, h2.y, h2.z, h2.w, h3.x, h3.y, h3.z, h3.w};
    float s = bs;
    #pragma unroll
    for (int k = 0; k < 16; ++k) s += hr[k] * (pw[k * 2] + pw[k * 2 + 1]);
    out[i] = s;
    float4* op = (float4*)(out + N_NODES + (size_t)i * 16);
    op[0] = h0; op[1] = h1; op[2] = h2; op[3] = h3;
}

// ---------------------------------------------------------------------------
extern "C" void kernel_launch(void* const* d_in, const int* in_sizes, int n_in,
                              void* d_out, int out_size) {
    const float* x   = (const float*)d_in[0];
    const float* W1  = (const float*)d_in[1];
    const float* b1  = (const float*)d_in[2];
    const float* W2  = (const float*)d_in[3];
    const float* b2  = (const float*)d_in[4];
    const float* cw0 = (const float*)d_in[5];
    const float* cb0 = (const float*)d_in[6];
    const float* cw1 = (const float*)d_in[7];
    const float* cb1 = (const float*)d_in[8];
    const float* pw  = (const float*)d_in[9];
    const float* pb  = (const float*)d_in[10];
    const int*   ei  = (const int*)d_in[11];
    float* out = (float*)d_out;

    k_zero<<<782, 256>>>();
    k_deg<<<N_EDGES / 256, 256>>>(ei);
    k_dinv<<<782, 256>>>();

    k_mlp<<<N_NODES / 32, 256>>>(x, W1, b1, W2, b2);

    // conv layer 0
    k_t<<<782, 256>>>(cw0);
    k_scatter<<<(4 * N_EDGES) / 256, 256>>>(ei);
    k_fin<<<(N_NODES * 4) / 256, 256>>>(cb0);

    // conv layer 1
    k_t<<<782, 256>>>(cw1);
    k_scatter<<<(4 * N_EDGES) / 256, 256>>>(ei);
    k_fin<<<(N_NODES * 4) / 256, 256>>>(cb1);

    k_out<<<782, 256>>>(pw, pb, out);
}

// round 3
// speedup vs baseline: 1.2744x; 1.2744x over previous
#include <cuda_runtime.h>
#include <cstdint>

#define N_NODES 200000
#define N_EDGES 6400000
#define IN_DIM  128
#define H1      256
#define HID     16
#define NEG     0.01f

// ---------------- scratch (device globals; no runtime allocation) ----------
__device__ __align__(16) float g_dinv[N_NODES];
__device__ __align__(16) float g_h  [N_NODES * HID];
__device__ __align__(16) float g_t  [N_NODES * HID];
__device__ __align__(16) float g_acc[N_NODES * HID];
__device__ __align__(16) float g_w1t[H1 * IN_DIM];          // [256][128] = W1^T (K-major)
__device__ __align__(16) float g_hidden[(size_t)200064 * H1]; // [N pad][256] layer-1 activations

__device__ __forceinline__ float lrelu(float v) { return v >= 0.f ? v : NEG * v; }

__device__ __forceinline__ void red_add_v4(float* p, float4 v) {
    asm volatile("red.global.add.v4.f32 [%0], {%1,%2,%3,%4};"
                 :: "l"(p), "f"(v.x), "f"(v.y), "f"(v.z), "f"(v.w) : "memory");
}

__device__ __forceinline__ uint32_t f2tf32(float f) {
    uint32_t r;
    asm("cvt.rna.tf32.f32 %0, %1;" : "=r"(r) : "f"(f));
    return r;
}

__device__ __forceinline__ void mma_tf32(float* c, const uint32_t* a, const uint32_t* b) {
    asm volatile("mma.sync.aligned.m16n8k8.row.col.f32.tf32.tf32.f32 "
                 "{%0,%1,%2,%3}, {%4,%5,%6,%7}, {%8,%9}, {%0,%1,%2,%3};"
                 : "+f"(c[0]), "+f"(c[1]), "+f"(c[2]), "+f"(c[3])
                 : "r"(a[0]), "r"(a[1]), "r"(a[2]), "r"(a[3]), "r"(b[0]), "r"(b[1]));
}

// ---------------- degree / dinv --------------------------------------------
__global__ __launch_bounds__(256) void k_zero() {
    int i = blockIdx.x * 256 + threadIdx.x;
    if (i < N_NODES) g_dinv[i] = 0.f;
}
__global__ __launch_bounds__(256) void k_deg(const int* __restrict__ ei) {
    int e = blockIdx.x * 256 + threadIdx.x;
    int dst = ei[N_EDGES + e];
    atomicAdd(&g_dinv[dst], 1.0f);
}
__global__ __launch_bounds__(256) void k_dinv() {
    int i = blockIdx.x * 256 + threadIdx.x;
    if (i < N_NODES) g_dinv[i] = rsqrtf(g_dinv[i] + 1.0f);
}

// ---------------- one-time W1 transpose ------------------------------------
__global__ __launch_bounds__(256) void k_wt(const float* __restrict__ W1) {
    int i = blockIdx.x * 256 + threadIdx.x;            // 128 blocks -> 32768
    int n = i >> 7, k = i & 127;
    g_w1t[i] = W1[k * H1 + n];
}

// ---------------- GEMM1 on tensor cores (tf32 mma.sync) --------------------
// CTA: 128 rows x 256 cols, 256 threads (8 warps).
// warp tile: 32 rows x 64 cols, two passes over N halves.
// smem: s_x [128][132] tf32 bits (67584B) | s_w [128][36] (18432B) | s_b1 (1024B)
#define SX_STRIDE 132
#define SW_STRIDE 36
#define SM_SW_OFF  (128 * SX_STRIDE)          // in words
#define SM_B1_OFF  (SM_SW_OFF + 128 * SW_STRIDE)
#define SM1_WORDS  (SM_B1_OFF + 256)
#define SM1_BYTES  (SM1_WORDS * 4)

__global__ __launch_bounds__(256, 2) void k_gemm1(const float* __restrict__ x,
                                                  const float* __restrict__ b1v) {
    extern __shared__ uint32_t sm[];
    uint32_t* s_x = sm;
    uint32_t* s_w = sm + SM_SW_OFF;
    float*    s_b1 = (float*)(sm + SM_B1_OFF);

    const int tid = threadIdx.x, wid = tid >> 5, lane = tid & 31;
    const int rowbase = blockIdx.x * 128;
    const int mrow = (wid & 3) * 32;          // warp row offset
    const int wcol = (wid >> 2) * 64;         // warp col offset within half

    if (tid < 256) s_b1[tid] = b1v[tid];

    // stage x tile (convert to tf32)
    for (int i = tid; i < 128 * 32; i += 256) {
        int r = i >> 5, k4 = (i & 31) * 4;
        float4 v = make_float4(0.f, 0.f, 0.f, 0.f);
        int gr = rowbase + r;
        if (gr < N_NODES) v = *(const float4*)(x + (size_t)gr * IN_DIM + k4);
        uint32_t* d = &s_x[r * SX_STRIDE + k4];
        d[0] = f2tf32(v.x); d[1] = f2tf32(v.y); d[2] = f2tf32(v.z); d[3] = f2tf32(v.w);
    }

    const int qrow = lane >> 2;      // 0..7
    const int qcol = lane & 3;       // 0..3

    for (int nh = 0; nh < 2; ++nh) {
        float c[2][8][4];
        #pragma unroll
        for (int mi = 0; mi < 2; ++mi)
            #pragma unroll
            for (int ni = 0; ni < 8; ++ni)
                #pragma unroll
                for (int q = 0; q < 4; ++q) c[mi][ni][q] = 0.f;

        for (int kc = 0; kc < 4; ++kc) {
            __syncthreads();
            // stage W1T chunk: rows = n in [nh*128, nh*128+128), cols kc*32..+31
            for (int i = tid; i < 128 * 8; i += 256) {
                int n = i >> 3, k4 = (i & 7) * 4;
                float4 v = *(const float4*)(g_w1t + (size_t)(nh * 128 + n) * IN_DIM + kc * 32 + k4);
                uint32_t* d = &s_w[n * SW_STRIDE + k4];
                d[0] = f2tf32(v.x); d[1] = f2tf32(v.y); d[2] = f2tf32(v.z); d[3] = f2tf32(v.w);
            }
            __syncthreads();

            #pragma unroll
            for (int ks = 0; ks < 4; ++ks) {
                const int kk = ks * 8;
                uint32_t afr[2][4];
                #pragma unroll
                for (int mi = 0; mi < 2; ++mi) {
                    const uint32_t* p = &s_x[(mrow + mi * 16 + qrow) * SX_STRIDE + kc * 32 + kk + qcol];
                    afr[mi][0] = p[0];
                    afr[mi][1] = p[8 * SX_STRIDE];
                    afr[mi][2] = p[4];
                    afr[mi][3] = p[8 * SX_STRIDE + 4];
                }
                uint32_t bfr[8][2];
                #pragma unroll
                for (int ni = 0; ni < 8; ++ni) {
                    const uint32_t* p = &s_w[(wcol + ni * 8 + qrow) * SW_STRIDE + kk + qcol];
                    bfr[ni][0] = p[0];
                    bfr[ni][1] = p[4];
                }
                #pragma unroll
                for (int mi = 0; mi < 2; ++mi)
                    #pragma unroll
                    for (int ni = 0; ni < 8; ++ni)
                        mma_tf32(c[mi][ni], afr[mi], bfr[ni]);
            }
        }

        // epilogue: bias + leaky -> g_hidden
        #pragma unroll
        for (int mi = 0; mi < 2; ++mi) {
            int r0 = rowbase + mrow + mi * 16 + qrow;
            #pragma unroll
            for (int ni = 0; ni < 8; ++ni) {
                int cg = nh * 128 + wcol + ni * 8 + qcol * 2;
                float bb0 = s_b1[cg], bb1 = s_b1[cg + 1];
                if (r0 < N_NODES) {
                    float2 v = make_float2(lrelu(c[mi][ni][0] + bb0), lrelu(c[mi][ni][1] + bb1));
                    *(float2*)(g_hidden + (size_t)r0 * H1 + cg) = v;
                }
                if (r0 + 8 < N_NODES) {
                    float2 v = make_float2(lrelu(c[mi][ni][2] + bb0), lrelu(c[mi][ni][3] + bb1));
                    *(float2*)(g_hidden + (size_t)(r0 + 8) * H1 + cg) = v;
                }
            }
        }
    }
}

// ---------------- layer 2: h = lrelu(hidden @ W2 + b2) ---------------------
__global__ __launch_bounds__(256) void k_h2(const float* __restrict__ W2,
                                            const float* __restrict__ b2) {
    __shared__ float s_w2[H1 * HID];     // 16KB
    __shared__ float s_b2[HID];
    for (int i = threadIdx.x; i < H1 * HID; i += 256) s_w2[i] = W2[i];
    if (threadIdx.x < HID) s_b2[threadIdx.x] = b2[threadIdx.x];
    __syncthreads();

    int i = blockIdx.x * 256 + threadIdx.x;
    if (i >= N_NODES) return;

    float acc[16];
    #pragma unroll
    for (int j = 0; j < 16; ++j) acc[j] = s_b2[j];

    const float4* hp = (const float4*)(g_hidden + (size_t)i * H1);
    #pragma unroll 4
    for (int c4 = 0; c4 < 64; ++c4) {
        float4 hv = hp[c4];
        float he[4] = {hv.x, hv.y, hv.z, hv.w};
        #pragma unroll
        for (int e = 0; e < 4; ++e) {
            const float* w = &s_w2[(c4 * 4 + e) * 16];
            float h = he[e];
            #pragma unroll
            for (int j4 = 0; j4 < 4; ++j4) {
                float4 wv = *(const float4*)(w + j4 * 4);
                acc[j4 * 4 + 0] += h * wv.x;
                acc[j4 * 4 + 1] += h * wv.y;
                acc[j4 * 4 + 2] += h * wv.z;
                acc[j4 * 4 + 3] += h * wv.w;
            }
        }
    }
    float4* op = (float4*)(g_h + (size_t)i * 16);
    #pragma unroll
    for (int q = 0; q < 4; ++q)
        op[q] = make_float4(lrelu(acc[q*4+0]), lrelu(acc[q*4+1]),
                            lrelu(acc[q*4+2]), lrelu(acc[q*4+3]));
}

// ---------------- t = dinv * (h @ W);  acc = t (self-loop seed) ------------
__global__ __launch_bounds__(256) void k_t(const float* __restrict__ W) {
    __shared__ float Ws[256];
    Ws[threadIdx.x] = W[threadIdx.x];
    __syncthreads();
    int i = blockIdx.x * 256 + threadIdx.x;
    if (i >= N_NODES) return;

    const float4* hp = (const float4*)(g_h + (size_t)i * 16);
    float4 h0 = hp[0], h1 = hp[1], h2 = hp[2], h3 = hp[3];
    float hr[16] = {h0.x, h0.y, h0.z, h0.w, h1.x, h1.y, h1.z, h1.w,
                    h2.x, h2.y, h2.z, h2.w, h3.x, h3.y, h3.z, h3.w};
    float acc[16];
    #pragma unroll
    for (int j = 0; j < 16; ++j) acc[j] = 0.f;
    #pragma unroll
    for (int k = 0; k < 16; ++k) {
        float hv = hr[k];
        #pragma unroll
        for (int j = 0; j < 16; ++j) acc[j] += hv * Ws[k * 16 + j];
    }
    float d = g_dinv[i];
    float4* tp = (float4*)(g_t + (size_t)i * 16);
    float4* ap = (float4*)(g_acc + (size_t)i * 16);
    #pragma unroll
    for (int q = 0; q < 4; ++q) {
        float4 v = make_float4(acc[q*4+0]*d, acc[q*4+1]*d, acc[q*4+2]*d, acc[q*4+3]*d);
        tp[q] = v;
        ap[q] = v;
    }
}

// ---------------- edge scatter: acc[dst] += t[src]  (4 threads / edge) -----
__global__ __launch_bounds__(256) void k_scatter(const int* __restrict__ ei) {
    unsigned gt = blockIdx.x * 256u + threadIdx.x;
    int e = gt >> 2, p = gt & 3;
    int src = ei[e];
    int dst = ei[N_EDGES + e];
    float4 v = *(const float4*)(g_t + (size_t)src * 16 + p * 4);
    red_add_v4(g_acc + (size_t)dst * 16 + p * 4, v);
}

// ---------------- finalize: h = lrelu(dinv*acc + b) ------------------------
__global__ __launch_bounds__(256) void k_fin(const float* __restrict__ b) {
    int idx = blockIdx.x * 256 + threadIdx.x;
    int node = idx >> 2, q = idx & 3;
    float d = g_dinv[node];
    float4 a  = *(const float4*)(g_acc + (size_t)idx * 4);
    float4 bv = *(const float4*)(b + q * 4);
    float4 r;
    r.x = lrelu(d * a.x + bv.x);
    r.y = lrelu(d * a.y + bv.y);
    r.z = lrelu(d * a.z + bv.z);
    r.w = lrelu(d * a.w + bv.w);
    *(float4*)(g_h + (size_t)idx * 4) = r;
}

// ---------------- head -----------------------------------------------------
__global__ __launch_bounds__(256) void k_out(const float* __restrict__ pw,
                                             const float* __restrict__ pb,
                                             float* __restrict__ out) {
    int i = blockIdx.x * 256 + threadIdx.x;
    if (i >= N_NODES) return;
    float bs = pb[0] + pb[1];
    const float4* hp = (const float4*)(g_h + (size_t)i * 16);
    float4 h0 = hp[0], h1 = hp[1], h2 = hp[2], h3 = hp[3];
    float hr[16] = {h0.x, h0.y, h0.z, h0.w, h1.x, h1.y, h1.z, h1.w,
                    h2.x, h2.y, h2.z, h2.w, h3.x, h3.y, h3.z, h3.w};
    float s = bs;
    #pragma unroll
    for (int k = 0; k < 16; ++k) s += hr[k] * (pw[k * 2] + pw[k * 2 + 1]);
    out[i] = s;
    float4* op = (float4*)(out + N_NODES + (size_t)i * 16);
    op[0] = h0; op[1] = h1; op[2] = h2; op[3] = h3;
}

// ---------------------------------------------------------------------------
extern "C" void kernel_launch(void* const* d_in, const int* in_sizes, int n_in,
                              void* d_out, int out_size) {
    const float* x   = (const float*)d_in[0];
    const float* W1  = (const float*)d_in[1];
    const float* b1  = (const float*)d_in[2];
    const float* W2  = (const float*)d_in[3];
    const float* b2  = (const float*)d_in[4];
    const float* cw0 = (const float*)d_in[5];
    const float* cb0 = (const float*)d_in[6];
    const float* cw1 = (const float*)d_in[7];
    const float* cb1 = (const float*)d_in[8];
    const float* pw  = (const float*)d_in[9];
    const float* pb  = (const float*)d_in[10];
    const int*   ei  = (const int*)d_in[11];
    float* out = (float*)d_out;

    static int smem_set = 0;
    if (!smem_set) {
        cudaFuncSetAttribute(k_gemm1, cudaFuncAttributeMaxDynamicSharedMemorySize, SM1_BYTES);
        smem_set = 1;
    }

    k_zero<<<782, 256>>>();
    k_deg<<<N_EDGES / 256, 256>>>(ei);
    k_dinv<<<782, 256>>>();
    k_wt<<<128, 256>>>(W1);

    k_gemm1<<<(N_NODES + 127) / 128, 256, SM1_BYTES>>>(x, b1);
    k_h2<<<782, 256>>>(W2, b2);

    // conv layer 0
    k_t<<<782, 256>>>(cw0);
    k_scatter<<<(4 * N_EDGES) / 256, 256>>>(ei);
    k_fin<<<(N_NODES * 4) / 256, 256>>>(cb0);

    // conv layer 1
    k_t<<<782, 256>>>(cw1);
    k_scatter<<<(4 * N_EDGES) / 256, 256>>>(ei);
    k_fin<<<(N_NODES * 4) / 256, 256>>>(cb1);

    k_out<<<782, 256>>>(pw, pb, out);
}

// round 4
// speedup vs baseline: 1.7629x; 1.3834x over previous
#include <cuda_runtime.h>
#include <cuda_fp16.h>
#include <cstdint>

#define N_NODES 200000
#define N_EDGES 6400000
#define IN_DIM  128
#define H1      256
#define HID     16
#define NEG     0.01f

// ---------------- scratch (device globals; no runtime allocation) ----------
__device__ __align__(16) float  g_dinv[N_NODES];
__device__ __align__(16) float  g_h  [N_NODES * HID];
__device__ __align__(16) float  g_t  [N_NODES * HID];
__device__ __align__(16) float  g_acc[N_NODES * HID];
__device__ __align__(16) __half g_w1h[H1 * IN_DIM];   // [256][128] = W1^T fp16
__device__ __align__(16) __half g_w2h[HID * H1];      // [16][256]  = W2^T fp16

__device__ __forceinline__ float lrelu(float v) { return v >= 0.f ? v : NEG * v; }

__device__ __forceinline__ void red_add_v4(float* p, float4 v) {
    asm volatile("red.global.add.v4.f32 [%0], {%1,%2,%3,%4};"
                 :: "l"(p), "f"(v.x), "f"(v.y), "f"(v.z), "f"(v.w) : "memory");
}

__device__ __forceinline__ void mma_f16(float* c, const uint32_t* a, const uint32_t* b) {
    asm volatile("mma.sync.aligned.m16n8k16.row.col.f32.f16.f16.f32 "
                 "{%0,%1,%2,%3}, {%4,%5,%6,%7}, {%8,%9}, {%0,%1,%2,%3};"
                 : "+f"(c[0]), "+f"(c[1]), "+f"(c[2]), "+f"(c[3])
                 : "r"(a[0]), "r"(a[1]), "r"(a[2]), "r"(a[3]), "r"(b[0]), "r"(b[1]));
}

// ---------------- degree / dinv --------------------------------------------
__global__ __launch_bounds__(256) void k_zero() {
    int i = blockIdx.x * 256 + threadIdx.x;
    if (i < N_NODES) g_dinv[i] = 0.f;
}
__global__ __launch_bounds__(256) void k_deg(const int* __restrict__ ei) {
    int e = blockIdx.x * 256 + threadIdx.x;
    int dst = ei[N_EDGES + e];
    atomicAdd(&g_dinv[dst], 1.0f);
}
__global__ __launch_bounds__(256) void k_dinv() {
    int i = blockIdx.x * 256 + threadIdx.x;
    if (i < N_NODES) g_dinv[i] = rsqrtf(g_dinv[i] + 1.0f);
}

// ---------------- one-time weight transpose+convert to fp16 ----------------
__global__ __launch_bounds__(256) void k_wt(const float* __restrict__ W1,
                                            const float* __restrict__ W2) {
    int i = blockIdx.x * 256 + threadIdx.x;            // 144*256 = 36864
    if (i < H1 * IN_DIM) {
        int n = i >> 7, k = i & 127;
        g_w1h[i] = __float2half_rn(W1[k * H1 + n]);
    } else {
        int j = i - H1 * IN_DIM;                       // < 4096
        int n = j >> 8, k = j & 255;
        g_w2h[j] = __float2half_rn(W2[k * HID + n]);
    }
}

// ---------------- fused MLP: h = lrelu(lrelu(x@W1+b1)@W2+b2) ---------------
// CTA: 256 rows, 512 threads (16 warps). warp tile 32 rows x 64 cols, 2 N-passes.
// GEMM2 fused: hidden stays in registers (C-frag layout == fp16 A-frag layout).
// smem halves:  s_x [256][136]  s_w1 [256][136]  s_w2 [16][264]
// smem floats:  s_red [256][20]  s_b1[256]  s_b2[16]
#define SX_H   0
#define SW1_H  34816
#define SW2_H  69632
#define SRED_B 147712
#define SB1_B  168192
#define SB2_B  169216
#define SMEM_MLP 169280

__global__ __launch_bounds__(512, 1) void k_mlp(const float* __restrict__ x,
                                                const float* __restrict__ b1v,
                                                const float* __restrict__ b2v) {
    extern __shared__ char smem[];
    __half* s_x  = (__half*)smem + SX_H;
    __half* s_w1 = (__half*)smem + SW1_H;
    __half* s_w2 = (__half*)smem + SW2_H;
    float*  s_red = (float*)(smem + SRED_B);
    float*  s_b1  = (float*)(smem + SB1_B);
    float*  s_b2  = (float*)(smem + SB2_B);

    const int tid = threadIdx.x, wid = tid >> 5, lane = tid & 31;
    const int qrow = lane >> 2, qcol = lane & 3;
    const int mrow = (wid & 7) * 32;         // warp row offset (0..224)
    const int wcol = (wid >> 3) * 64;        // warp K-col offset within half
    const int rowbase = blockIdx.x * 256;

    if (tid < 256) s_b1[tid] = b1v[tid];
    if (tid < 16)  s_b2[tid] = b2v[tid];

    // stage x tile as fp16 (256 rows x 128 cols, stride 136)
    for (int i = tid; i < 256 * 32; i += 512) {
        int r = i >> 5, k4 = (i & 31) * 4;
        float4 v = make_float4(0.f, 0.f, 0.f, 0.f);
        int gr = rowbase + r;
        if (gr < N_NODES) v = *(const float4*)(x + (size_t)gr * IN_DIM + k4);
        __half2 h0 = __floats2half2_rn(v.x, v.y);
        __half2 h1 = __floats2half2_rn(v.z, v.w);
        uint2 u = make_uint2(*(uint32_t*)&h0, *(uint32_t*)&h1);
        *(uint2*)&s_x[r * 136 + k4] = u;
    }
    // stage full W1T fp16 (256 x 128, stride 136)
    for (int i = tid; i < 256 * 32; i += 512) {
        int n = i >> 5, k4 = (i & 31) * 4;
        uint2 u = *(const uint2*)&g_w1h[n * IN_DIM + k4];
        *(uint2*)&s_w1[n * 136 + k4] = u;
    }
    // stage W2T fp16 (16 x 256, stride 264)
    for (int i = tid; i < 16 * 64; i += 512) {
        int n = i >> 6, k4 = (i & 63) * 4;
        uint2 u = *(const uint2*)&g_w2h[n * H1 + k4];
        *(uint2*)&s_w2[n * 264 + k4] = u;
    }
    __syncthreads();

    float d[2][2][4];
    #pragma unroll
    for (int mi = 0; mi < 2; ++mi)
        #pragma unroll
        for (int nt = 0; nt < 2; ++nt)
            #pragma unroll
            for (int q = 0; q < 4; ++q) d[mi][nt][q] = 0.f;

    #pragma unroll 1
    for (int nh = 0; nh < 2; ++nh) {
        float c[2][8][4];
        #pragma unroll
        for (int mi = 0; mi < 2; ++mi)
            #pragma unroll
            for (int ni = 0; ni < 8; ++ni)
                #pragma unroll
                for (int q = 0; q < 4; ++q) c[mi][ni][q] = 0.f;

        // GEMM1: K=128, 8 slices of k16
        #pragma unroll 2
        for (int ks = 0; ks < 8; ++ks) {
            const int kk = ks * 16;
            uint32_t a[2][4];
            #pragma unroll
            for (int mi = 0; mi < 2; ++mi) {
                const __half* p = &s_x[(mrow + mi * 16 + qrow) * 136 + kk + qcol * 2];
                a[mi][0] = *(const uint32_t*)p;
                a[mi][1] = *(const uint32_t*)(p + 8 * 136);
                a[mi][2] = *(const uint32_t*)(p + 8);
                a[mi][3] = *(const uint32_t*)(p + 8 * 136 + 8);
            }
            uint32_t b[8][2];
            #pragma unroll
            for (int ni = 0; ni < 8; ++ni) {
                const __half* p = &s_w1[(nh * 128 + wcol + ni * 8 + qrow) * 136 + kk + qcol * 2];
                b[ni][0] = *(const uint32_t*)p;
                b[ni][1] = *(const uint32_t*)(p + 8);
            }
            #pragma unroll
            for (int mi = 0; mi < 2; ++mi)
                #pragma unroll
                for (int ni = 0; ni < 8; ++ni)
                    mma_f16(c[mi][ni], a[mi], b[ni]);
        }

        // epilogue: bias+leaky -> fp16 A-frags -> fused GEMM2 partial
        #pragma unroll
        for (int mi = 0; mi < 2; ++mi) {
            uint32_t ah[8][2];
            #pragma unroll
            for (int ni = 0; ni < 8; ++ni) {
                int col0 = nh * 128 + wcol + ni * 8 + qcol * 2;
                float bb0 = s_b1[col0], bb1 = s_b1[col0 + 1];
                float f0 = lrelu(c[mi][ni][0] + bb0);
                float f1 = lrelu(c[mi][ni][1] + bb1);
                float f2 = lrelu(c[mi][ni][2] + bb0);
                float f3 = lrelu(c[mi][ni][3] + bb1);
                __half2 h01 = __floats2half2_rn(f0, f1);
                __half2 h23 = __floats2half2_rn(f2, f3);
                ah[ni][0] = *(uint32_t*)&h01;
                ah[ni][1] = *(uint32_t*)&h23;
            }
            #pragma unroll
            for (int j = 0; j < 4; ++j) {
                uint32_t afr[4] = {ah[2*j][0], ah[2*j][1], ah[2*j+1][0], ah[2*j+1][1]};
                int kg = nh * 128 + wcol + j * 16;
                #pragma unroll
                for (int nt = 0; nt < 2; ++nt) {
                    const __half* p = &s_w2[(nt * 8 + qrow) * 264 + kg + qcol * 2];
                    uint32_t bb[2] = {*(const uint32_t*)p, *(const uint32_t*)(p + 8)};
                    mma_f16(d[mi][nt], afr, bb);
                }
            }
        }
    }

    // cross-warp reduction of the two K-halves (wcol 0 vs 64)
    if (wid >= 8) {
        #pragma unroll
        for (int mi = 0; mi < 2; ++mi)
            #pragma unroll
            for (int nt = 0; nt < 2; ++nt)
                #pragma unroll
                for (int q = 0; q < 4; ++q) {
                    int rl = mrow + mi * 16 + qrow + (q >> 1) * 8;
                    int col = nt * 8 + qcol * 2 + (q & 1);
                    s_red[rl * 20 + col] = d[mi][nt][q];
                }
    }
    __syncthreads();
    if (wid < 8) {
        #pragma unroll
        for (int mi = 0; mi < 2; ++mi)
            #pragma unroll
            for (int nt = 0; nt < 2; ++nt)
                #pragma unroll
                for (int q = 0; q < 4; ++q) {
                    int rl = mrow + mi * 16 + qrow + (q >> 1) * 8;
                    int col = nt * 8 + qcol * 2 + (q & 1);
                    float v = d[mi][nt][q] + s_red[rl * 20 + col];
                    s_red[rl * 20 + col] = lrelu(v + s_b2[col]);
                }
    }
    __syncthreads();
    {
        int r = tid >> 1, part = tid & 1;
        int gr = rowbase + r;
        if (gr < N_NODES) {
            float4 v0 = *(float4*)&s_red[r * 20 + part * 8];
            float4 v1 = *(float4*)&s_red[r * 20 + part * 8 + 4];
            *(float4*)(g_h + (size_t)gr * 16 + part * 8)     = v0;
            *(float4*)(g_h + (size_t)gr * 16 + part * 8 + 4) = v1;
        }
    }
}

// ---------------- t = dinv * (h @ W);  acc = t (self-loop seed) ------------
__global__ __launch_bounds__(256) void k_t(const float* __restrict__ W) {
    __shared__ float Ws[256];
    Ws[threadIdx.x] = W[threadIdx.x];
    __syncthreads();
    int i = blockIdx.x * 256 + threadIdx.x;
    if (i >= N_NODES) return;

    const float4* hp = (const float4*)(g_h + (size_t)i * 16);
    float4 h0 = hp[0], h1 = hp[1], h2 = hp[2], h3 = hp[3];
    float hr[16] = {h0.x, h0.y, h0.z, h0.w, h1.x, h1.y, h1.z, h1.w,
                    h2.x, h2.y, h2.z, h2.w, h3.x, h3.y, h3.z, h3.w};
    float acc[16];
    #pragma unroll
    for (int j = 0; j < 16; ++j) acc[j] = 0.f;
    #pragma unroll
    for (int k = 0; k < 16; ++k) {
        float hv = hr[k];
        #pragma unroll
        for (int j = 0; j < 16; ++j) acc[j] += hv * Ws[k * 16 + j];
    }
    float dv = g_dinv[i];
    float4* tp = (float4*)(g_t + (size_t)i * 16);
    float4* ap = (float4*)(g_acc + (size_t)i * 16);
    #pragma unroll
    for (int q = 0; q < 4; ++q) {
        float4 v = make_float4(acc[q*4+0]*dv, acc[q*4+1]*dv, acc[q*4+2]*dv, acc[q*4+3]*dv);
        tp[q] = v;
        ap[q] = v;
    }
}

// ---------------- edge scatter: acc[dst] += t[src]  (4 threads / edge) -----
__global__ __launch_bounds__(256) void k_scatter(const int* __restrict__ ei) {
    unsigned gt = blockIdx.x * 256u + threadIdx.x;
    int e = gt >> 2, p = gt & 3;
    int src = ei[e];
    int dst = ei[N_EDGES + e];
    float4 v = *(const float4*)(g_t + (size_t)src * 16 + p * 4);
    red_add_v4(g_acc + (size_t)dst * 16 + p * 4, v);
}

// ---------------- finalize: h = lrelu(dinv*acc + b) ------------------------
__global__ __launch_bounds__(256) void k_fin(const float* __restrict__ b) {
    int idx = blockIdx.x * 256 + threadIdx.x;
    int node = idx >> 2, q = idx & 3;
    float dv = g_dinv[node];
    float4 a  = *(const float4*)(g_acc + (size_t)idx * 4);
    float4 bv = *(const float4*)(b + q * 4);
    float4 r;
    r.x = lrelu(dv * a.x + bv.x);
    r.y = lrelu(dv * a.y + bv.y);
    r.z = lrelu(dv * a.z + bv.z);
    r.w = lrelu(dv * a.w + bv.w);
    *(float4*)(g_h + (size_t)idx * 4) = r;
}

// ---------------- head -----------------------------------------------------
__global__ __launch_bounds__(256) void k_out(const float* __restrict__ pw,
                                             const float* __restrict__ pb,
                                             float* __restrict__ out) {
    int i = blockIdx.x * 256 + threadIdx.x;
    if (i >= N_NODES) return;
    float bs = pb[0] + pb[1];
    const float4* hp = (const float4*)(g_h + (size_t)i * 16);
    float4 h0 = hp[0], h1 = hp[1], h2 = hp[2], h3 = hp[3];
    float hr[16] = {h0.x, h0.y, h0.z, h0.w, h1.x, h1.y, h1.z, h1.w,
                    h2.x, h2.y, h2.z, h2.w, h3.x, h3.y, h3.z, h3.w};
    float s = bs;
    #pragma unroll
    for (int k = 0; k < 16; ++k) s += hr[k] * (pw[k * 2] + pw[k * 2 + 1]);
    out[i] = s;
    float4* op = (float4*)(out + N_NODES + (size_t)i * 16);
    op[0] = h0; op[1] = h1; op[2] = h2; op[3] = h3;
}

// ---------------------------------------------------------------------------
extern "C" void kernel_launch(void* const* d_in, const int* in_sizes, int n_in,
                              void* d_out, int out_size) {
    const float* x   = (const float*)d_in[0];
    const float* W1  = (const float*)d_in[1];
    const float* b1  = (const float*)d_in[2];
    const float* W2  = (const float*)d_in[3];
    const float* b2  = (const float*)d_in[4];
    const float* cw0 = (const float*)d_in[5];
    const float* cb0 = (const float*)d_in[6];
    const float* cw1 = (const float*)d_in[7];
    const float* cb1 = (const float*)d_in[8];
    const float* pw  = (const float*)d_in[9];
    const float* pb  = (const float*)d_in[10];
    const int*   ei  = (const int*)d_in[11];
    float* out = (float*)d_out;

    static int smem_set = 0;
    if (!smem_set) {
        cudaFuncSetAttribute(k_mlp, cudaFuncAttributeMaxDynamicSharedMemorySize, SMEM_MLP);
        smem_set = 1;
    }

    k_zero<<<782, 256>>>();
    k_deg<<<N_EDGES / 256, 256>>>(ei);
    k_dinv<<<782, 256>>>();
    k_wt<<<144, 256>>>(W1, W2);

    k_mlp<<<782, 512, SMEM_MLP>>>(x, b1, b2);

    // conv layer 0
    k_t<<<782, 256>>>(cw0);
    k_scatter<<<(4 * N_EDGES) / 256, 256>>>(ei);
    k_fin<<<(N_NODES * 4) / 256, 256>>>(cb0);

    // conv layer 1
    k_t<<<782, 256>>>(cw1);
    k_scatter<<<(4 * N_EDGES) / 256, 256>>>(ei);
    k_fin<<<(N_NODES * 4) / 256, 256>>>(cb1);

    k_out<<<782, 256>>>(pw, pb, out);
}

// round 5
// speedup vs baseline: 2.0132x; 1.1419x over previous
#include <cuda_runtime.h>
#include <cuda_fp16.h>
#include <cstdint>

#define N_NODES 200000
#define N_EDGES 6400000
#define IN_DIM  128
#define H1      256
#define HID     16
#define NEG     0.01f
#define NBLK_SCAN 196   // ceil(200000/1024)

// ---------------- scratch (device globals; no runtime allocation) ----------
__device__ __align__(16) float  g_dinv[N_NODES];
__device__ __align__(16) float  g_h  [N_NODES * HID];
__device__ __align__(16) float  g_t  [N_NODES * HID];
__device__ __align__(16) __half g_w1h[H1 * IN_DIM];   // [256][128] = W1^T fp16
__device__ __align__(16) __half g_w2h[HID * H1];      // [16][256]  = W2^T fp16
__device__ __align__(16) int    g_deg[N_NODES];
__device__ __align__(16) int    g_row[N_NODES];       // CSR row starts (by dst)
__device__ __align__(16) int    g_cur[N_NODES];       // build cursors
__device__ __align__(16) int    g_col[N_EDGES];       // CSR: src per incoming edge
__device__              int     g_bsum[NBLK_SCAN];
__device__              int     g_boff[NBLK_SCAN];

__device__ __forceinline__ float lrelu(float v) { return v >= 0.f ? v : NEG * v; }

__device__ __forceinline__ void mma_f16(float* c, const uint32_t* a, const uint32_t* b) {
    asm volatile("mma.sync.aligned.m16n8k16.row.col.f32.f16.f16.f32 "
                 "{%0,%1,%2,%3}, {%4,%5,%6,%7}, {%8,%9}, {%0,%1,%2,%3};"
                 : "+f"(c[0]), "+f"(c[1]), "+f"(c[2]), "+f"(c[3])
                 : "r"(a[0]), "r"(a[1]), "r"(a[2]), "r"(a[3]), "r"(b[0]), "r"(b[1]));
}

// ---------------- CSR build: histogram, scan, bucket scatter ---------------
__global__ __launch_bounds__(256) void k_zero() {
    int i = blockIdx.x * 256 + threadIdx.x;
    if (i < N_NODES) g_deg[i] = 0;
}

__global__ __launch_bounds__(256) void k_hist(const int* __restrict__ ei) {
    int e = blockIdx.x * 256 + threadIdx.x;          // grid covers E exactly
    atomicAdd(&g_deg[ei[N_EDGES + e]], 1);
}

__global__ __launch_bounds__(256) void k_scan1() {
    __shared__ int s[256];
    const int tid = threadIdx.x;
    const int base = blockIdx.x * 1024 + tid * 4;
    int d0 = 0, d1 = 0, d2 = 0, d3 = 0;
    if (base + 3 < N_NODES) {
        int4 v = *(const int4*)&g_deg[base];
        d0 = v.x; d1 = v.y; d2 = v.z; d3 = v.w;
    } else {
        if (base + 0 < N_NODES) d0 = g_deg[base + 0];
        if (base + 1 < N_NODES) d1 = g_deg[base + 1];
        if (base + 2 < N_NODES) d2 = g_deg[base + 2];
        if (base + 3 < N_NODES) d3 = g_deg[base + 3];
    }
    int s0 = d0, s1 = s0 + d1, s2 = s1 + d2, s3 = s2 + d3;
    s[tid] = s3;
    __syncthreads();
    #pragma unroll
    for (int off = 1; off < 256; off <<= 1) {
        int v = (tid >= off) ? s[tid - off] : 0;
        __syncthreads();
        s[tid] += v;
        __syncthreads();
    }
    int excl = s[tid] - s3;
    if (base + 0 < N_NODES) g_row[base + 0] = excl;
    if (base + 1 < N_NODES) g_row[base + 1] = excl + s0;
    if (base + 2 < N_NODES) g_row[base + 2] = excl + s1;
    if (base + 3 < N_NODES) g_row[base + 3] = excl + s2;
    if (tid == 255) g_bsum[blockIdx.x] = s[255];
}

__global__ __launch_bounds__(256) void k_scan2() {
    __shared__ int s[256];
    const int tid = threadIdx.x;
    int v = (tid < NBLK_SCAN) ? g_bsum[tid] : 0;
    s[tid] = v;
    __syncthreads();
    #pragma unroll
    for (int off = 1; off < 256; off <<= 1) {
        int u = (tid >= off) ? s[tid - off] : 0;
        __syncthreads();
        s[tid] += u;
        __syncthreads();
    }
    if (tid < NBLK_SCAN) g_boff[tid] = s[tid] - v;
}

__global__ __launch_bounds__(256) void k_scan3() {
    int i = blockIdx.x * 256 + threadIdx.x;
    if (i >= N_NODES) return;
    int start = g_row[i] + g_boff[i >> 10];
    g_row[i] = start;
    g_cur[i] = start;
    g_dinv[i] = rsqrtf((float)g_deg[i] + 1.0f);
}

__global__ __launch_bounds__(256) void k_build(const int* __restrict__ ei) {
    int e = blockIdx.x * 256 + threadIdx.x;          // grid covers E exactly
    int src = ei[e];
    int dst = ei[N_EDGES + e];
    int pos = atomicAdd(&g_cur[dst], 1);
    g_col[pos] = src;
}

// ---------------- one-time weight transpose+convert to fp16 ----------------
__global__ __launch_bounds__(256) void k_wt(const float* __restrict__ W1,
                                            const float* __restrict__ W2) {
    int i = blockIdx.x * 256 + threadIdx.x;            // 144*256 = 36864
    if (i < H1 * IN_DIM) {
        int n = i >> 7, k = i & 127;
        g_w1h[i] = __float2half_rn(W1[k * H1 + n]);
    } else {
        int j = i - H1 * IN_DIM;                       // < 4096
        int n = j >> 8, k = j & 255;
        g_w2h[j] = __float2half_rn(W2[k * HID + n]);
    }
}

// ---------------- fused MLP: h = lrelu(lrelu(x@W1+b1)@W2+b2) ---------------
#define SX_H   0
#define SW1_H  34816
#define SW2_H  69632
#define SRED_B 147712
#define SB1_B  168192
#define SB2_B  169216
#define SMEM_MLP 169280

__global__ __launch_bounds__(512, 1) void k_mlp(const float* __restrict__ x,
                                                const float* __restrict__ b1v,
                                                const float* __restrict__ b2v) {
    extern __shared__ char smem[];
    __half* s_x  = (__half*)smem + SX_H;
    __half* s_w1 = (__half*)smem + SW1_H;
    __half* s_w2 = (__half*)smem + SW2_H;
    float*  s_red = (float*)(smem + SRED_B);
    float*  s_b1  = (float*)(smem + SB1_B);
    float*  s_b2  = (float*)(smem + SB2_B);

    const int tid = threadIdx.x, wid = tid >> 5, lane = tid & 31;
    const int qrow = lane >> 2, qcol = lane & 3;
    const int mrow = (wid & 7) * 32;
    const int wcol = (wid >> 3) * 64;
    const int rowbase = blockIdx.x * 256;

    if (tid < 256) s_b1[tid] = b1v[tid];
    if (tid < 16)  s_b2[tid] = b2v[tid];

    for (int i = tid; i < 256 * 32; i += 512) {
        int r = i >> 5, k4 = (i & 31) * 4;
        float4 v = make_float4(0.f, 0.f, 0.f, 0.f);
        int gr = rowbase + r;
        if (gr < N_NODES) v = *(const float4*)(x + (size_t)gr * IN_DIM + k4);
        __half2 h0 = __floats2half2_rn(v.x, v.y);
        __half2 h1 = __floats2half2_rn(v.z, v.w);
        uint2 u = make_uint2(*(uint32_t*)&h0, *(uint32_t*)&h1);
        *(uint2*)&s_x[r * 136 + k4] = u;
    }
    for (int i = tid; i < 256 * 32; i += 512) {
        int n = i >> 5, k4 = (i & 31) * 4;
        uint2 u = *(const uint2*)&g_w1h[n * IN_DIM + k4];
        *(uint2*)&s_w1[n * 136 + k4] = u;
    }
    for (int i = tid; i < 16 * 64; i += 512) {
        int n = i >> 6, k4 = (i & 63) * 4;
        uint2 u = *(const uint2*)&g_w2h[n * H1 + k4];
        *(uint2*)&s_w2[n * 264 + k4] = u;
    }
    __syncthreads();

    float d[2][2][4];
    #pragma unroll
    for (int mi = 0; mi < 2; ++mi)
        #pragma unroll
        for (int nt = 0; nt < 2; ++nt)
            #pragma unroll
            for (int q = 0; q < 4; ++q) d[mi][nt][q] = 0.f;

    #pragma unroll 1
    for (int nh = 0; nh < 2; ++nh) {
        float c[2][8][4];
        #pragma unroll
        for (int mi = 0; mi < 2; ++mi)
            #pragma unroll
            for (int ni = 0; ni < 8; ++ni)
                #pragma unroll
                for (int q = 0; q < 4; ++q) c[mi][ni][q] = 0.f;

        #pragma unroll 2
        for (int ks = 0; ks < 8; ++ks) {
            const int kk = ks * 16;
            uint32_t a[2][4];
            #pragma unroll
            for (int mi = 0; mi < 2; ++mi) {
                const __half* p = &s_x[(mrow + mi * 16 + qrow) * 136 + kk + qcol * 2];
                a[mi][0] = *(const uint32_t*)p;
                a[mi][1] = *(const uint32_t*)(p + 8 * 136);
                a[mi][2] = *(const uint32_t*)(p + 8);
                a[mi][3] = *(const uint32_t*)(p + 8 * 136 + 8);
            }
            uint32_t b[8][2];
            #pragma unroll
            for (int ni = 0; ni < 8; ++ni) {
                const __half* p = &s_w1[(nh * 128 + wcol + ni * 8 + qrow) * 136 + kk + qcol * 2];
                b[ni][0] = *(const uint32_t*)p;
                b[ni][1] = *(const uint32_t*)(p + 8);
            }
            #pragma unroll
            for (int mi = 0; mi < 2; ++mi)
                #pragma unroll
                for (int ni = 0; ni < 8; ++ni)
                    mma_f16(c[mi][ni], a[mi], b[ni]);
        }

        #pragma unroll
        for (int mi = 0; mi < 2; ++mi) {
            uint32_t ah[8][2];
            #pragma unroll
            for (int ni = 0; ni < 8; ++ni) {
                int col0 = nh * 128 + wcol + ni * 8 + qcol * 2;
                float bb0 = s_b1[col0], bb1 = s_b1[col0 + 1];
                float f0 = lrelu(c[mi][ni][0] + bb0);
                float f1 = lrelu(c[mi][ni][1] + bb1);
                float f2 = lrelu(c[mi][ni][2] + bb0);
                float f3 = lrelu(c[mi][ni][3] + bb1);
                __half2 h01 = __floats2half2_rn(f0, f1);
                __half2 h23 = __floats2half2_rn(f2, f3);
                ah[ni][0] = *(uint32_t*)&h01;
                ah[ni][1] = *(uint32_t*)&h23;
            }
            #pragma unroll
            for (int j = 0; j < 4; ++j) {
                uint32_t afr[4] = {ah[2*j][0], ah[2*j][1], ah[2*j+1][0], ah[2*j+1][1]};
                int kg = nh * 128 + wcol + j * 16;
                #pragma unroll
                for (int nt = 0; nt < 2; ++nt) {
                    const __half* p = &s_w2[(nt * 8 + qrow) * 264 + kg + qcol * 2];
                    uint32_t bb[2] = {*(const uint32_t*)p, *(const uint32_t*)(p + 8)};
                    mma_f16(d[mi][nt], afr, bb);
                }
            }
        }
    }

    if (wid >= 8) {
        #pragma unroll
        for (int mi = 0; mi < 2; ++mi)
            #pragma unroll
            for (int nt = 0; nt < 2; ++nt)
                #pragma unroll
                for (int q = 0; q < 4; ++q) {
                    int rl = mrow + mi * 16 + qrow + (q >> 1) * 8;
                    int col = nt * 8 + qcol * 2 + (q & 1);
                    s_red[rl * 20 + col] = d[mi][nt][q];
                }
    }
    __syncthreads();
    if (wid < 8) {
        #pragma unroll
        for (int mi = 0; mi < 2; ++mi)
            #pragma unroll
            for (int nt = 0; nt < 2; ++nt)
                #pragma unroll
                for (int q = 0; q < 4; ++q) {
                    int rl = mrow + mi * 16 + qrow + (q >> 1) * 8;
                    int col = nt * 8 + qcol * 2 + (q & 1);
                    float v = d[mi][nt][q] + s_red[rl * 20 + col];
                    s_red[rl * 20 + col] = lrelu(v + s_b2[col]);
                }
    }
    __syncthreads();
    {
        int r = tid >> 1, part = tid & 1;
        int gr = rowbase + r;
        if (gr < N_NODES) {
            float4 v0 = *(float4*)&s_red[r * 20 + part * 8];
            float4 v1 = *(float4*)&s_red[r * 20 + part * 8 + 4];
            *(float4*)(g_h + (size_t)gr * 16 + part * 8)     = v0;
            *(float4*)(g_h + (size_t)gr * 16 + part * 8 + 4) = v1;
        }
    }
}

// ---------------- t = dinv * (h @ W) ---------------------------------------
__global__ __launch_bounds__(256) void k_t(const float* __restrict__ W) {
    __shared__ float Ws[256];
    Ws[threadIdx.x] = W[threadIdx.x];
    __syncthreads();
    int i = blockIdx.x * 256 + threadIdx.x;
    if (i >= N_NODES) return;

    const float4* hp = (const float4*)(g_h + (size_t)i * 16);
    float4 h0 = hp[0], h1 = hp[1], h2 = hp[2], h3 = hp[3];
    float hr[16] = {h0.x, h0.y, h0.z, h0.w, h1.x, h1.y, h1.z, h1.w,
                    h2.x, h2.y, h2.z, h2.w, h3.x, h3.y, h3.z, h3.w};
    float acc[16];
    #pragma unroll
    for (int j = 0; j < 16; ++j) acc[j] = 0.f;
    #pragma unroll
    for (int k = 0; k < 16; ++k) {
        float hv = hr[k];
        #pragma unroll
        for (int j = 0; j < 16; ++j) acc[j] += hv * Ws[k * 16 + j];
    }
    float dv = g_dinv[i];
    float4* tp = (float4*)(g_t + (size_t)i * 16);
    #pragma unroll
    for (int q = 0; q < 4; ++q)
        tp[q] = make_float4(acc[q*4+0]*dv, acc[q*4+1]*dv, acc[q*4+2]*dv, acc[q*4+3]*dv);
}

// ---------------- CSR gather: h = lrelu(dinv*(t_self + sum t[src]) + b) ----
__global__ __launch_bounds__(256) void k_gather(const float* __restrict__ b) {
    __shared__ float sb[16];
    if (threadIdx.x < 16) sb[threadIdx.x] = b[threadIdx.x];
    __syncthreads();
    int gid = blockIdx.x * 256 + threadIdx.x;
    int node = gid >> 2, q = gid & 3;
    if (node >= N_NODES) return;

    const int start = g_row[node];
    const int deg   = g_deg[node];
    const float* tq = g_t + q * 4;

    float4 acc = *(const float4*)(g_t + (size_t)node * 16 + q * 4);   // self loop
    int j = start, end = start + deg;
    for (; j + 1 < end; j += 2) {
        int s0 = __ldg(&g_col[j]);
        int s1 = __ldg(&g_col[j + 1]);
        float4 v0 = *(const float4*)(tq + (size_t)s0 * 16);
        float4 v1 = *(const float4*)(tq + (size_t)s1 * 16);
        acc.x += v0.x; acc.y += v0.y; acc.z += v0.z; acc.w += v0.w;
        acc.x += v1.x; acc.y += v1.y; acc.z += v1.z; acc.w += v1.w;
    }
    if (j < end) {
        int s0 = __ldg(&g_col[j]);
        float4 v0 = *(const float4*)(tq + (size_t)s0 * 16);
        acc.x += v0.x; acc.y += v0.y; acc.z += v0.z; acc.w += v0.w;
    }
    float dv = g_dinv[node];
    float4 bv = *(const float4*)&sb[q * 4];
    float4 r;
    r.x = lrelu(dv * acc.x + bv.x);
    r.y = lrelu(dv * acc.y + bv.y);
    r.z = lrelu(dv * acc.z + bv.z);
    r.w = lrelu(dv * acc.w + bv.w);
    *(float4*)(g_h + (size_t)node * 16 + q * 4) = r;
}

// ---------------- head -----------------------------------------------------
__global__ __launch_bounds__(256) void k_out(const float* __restrict__ pw,
                                             const float* __restrict__ pb,
                                             float* __restrict__ out) {
    int i = blockIdx.x * 256 + threadIdx.x;
    if (i >= N_NODES) return;
    float bs = pb[0] + pb[1];
    const float4* hp = (const float4*)(g_h + (size_t)i * 16);
    float4 h0 = hp[0], h1 = hp[1], h2 = hp[2], h3 = hp[3];
    float hr[16] = {h0.x, h0.y, h0.z, h0.w, h1.x, h1.y, h1.z, h1.w,
                    h2.x, h2.y, h2.z, h2.w, h3.x, h3.y, h3.z, h3.w};
    float s = bs;
    #pragma unroll
    for (int k = 0; k < 16; ++k) s += hr[k] * (pw[k * 2] + pw[k * 2 + 1]);
    out[i] = s;
    float4* op = (float4*)(out + N_NODES + (size_t)i * 16);
    op[0] = h0; op[1] = h1; op[2] = h2; op[3] = h3;
}

// ---------------------------------------------------------------------------
extern "C" void kernel_launch(void* const* d_in, const int* in_sizes, int n_in,
                              void* d_out, int out_size) {
    const float* x   = (const float*)d_in[0];
    const float* W1  = (const float*)d_in[1];
    const float* b1  = (const float*)d_in[2];
    const float* W2  = (const float*)d_in[3];
    const float* b2  = (const float*)d_in[4];
    const float* cw0 = (const float*)d_in[5];
    const float* cb0 = (const float*)d_in[6];
    const float* cw1 = (const float*)d_in[7];
    const float* cb1 = (const float*)d_in[8];
    const float* pw  = (const float*)d_in[9];
    const float* pb  = (const float*)d_in[10];
    const int*   ei  = (const int*)d_in[11];
    float* out = (float*)d_out;

    static int smem_set = 0;
    if (!smem_set) {
        cudaFuncSetAttribute(k_mlp, cudaFuncAttributeMaxDynamicSharedMemorySize, SMEM_MLP);
        smem_set = 1;
    }

    // CSR build
    k_zero<<<782, 256>>>();
    k_hist<<<N_EDGES / 256, 256>>>(ei);
    k_scan1<<<NBLK_SCAN, 256>>>();
    k_scan2<<<1, 256>>>();
    k_scan3<<<782, 256>>>();
    k_build<<<N_EDGES / 256, 256>>>(ei);

    k_wt<<<144, 256>>>(W1, W2);
    k_mlp<<<782, 512, SMEM_MLP>>>(x, b1, b2);

    // conv layer 0
    k_t<<<782, 256>>>(cw0);
    k_gather<<<(4 * N_NODES + 255) / 256, 256>>>(cb0);

    // conv layer 1
    k_t<<<782, 256>>>(cw1);
    k_gather<<<(4 * N_NODES + 255) / 256, 256>>>(cb1);

    k_out<<<782, 256>>>(pw, pb, out);
}

// round 6
// speedup vs baseline: 2.1219x; 1.0540x over previous
#include <cuda_runtime.h>
#include <cuda_fp16.h>
#include <cstdint>

#define N_NODES 200000
#define N_EDGES 6400000
#define IN_DIM  128
#define H1      256
#define HID     16
#define NEG     0.01f
#define NBLK_SCAN 196   // ceil(200000/1024)

// ---------------- scratch (device globals; no runtime allocation) ----------
__device__ __align__(16) float  g_dinv[N_NODES];
__device__ __align__(16) float  g_h  [N_NODES * HID];
__device__ __align__(16) __half g_t  [N_NODES * HID];  // fp16 messages (32B/row)
__device__ __align__(16) __half g_w1h[H1 * IN_DIM];    // [256][128] = W1^T fp16
__device__ __align__(16) __half g_w2h[HID * H1];       // [16][256]  = W2^T fp16
__device__ __align__(16) int    g_deg[N_NODES];
__device__ __align__(16) int    g_row[N_NODES];        // CSR row starts (by dst)
__device__ __align__(16) int    g_cur[N_NODES];        // build cursors
__device__ __align__(16) int    g_col[N_EDGES];        // CSR: src per incoming edge
__device__              int     g_bsum[NBLK_SCAN];
__device__              int     g_boff[NBLK_SCAN];

__device__ __forceinline__ float lrelu(float v) { return v >= 0.f ? v : NEG * v; }

__device__ __forceinline__ void mma_f16(float* c, const uint32_t* a, const uint32_t* b) {
    asm volatile("mma.sync.aligned.m16n8k16.row.col.f32.f16.f16.f32 "
                 "{%0,%1,%2,%3}, {%4,%5,%6,%7}, {%8,%9}, {%0,%1,%2,%3};"
                 : "+f"(c[0]), "+f"(c[1]), "+f"(c[2]), "+f"(c[3])
                 : "r"(a[0]), "r"(a[1]), "r"(a[2]), "r"(a[3]), "r"(b[0]), "r"(b[1]));
}

// ---------------- CSR build: histogram, scan, bucket scatter ---------------
__global__ __launch_bounds__(256) void k_zero() {
    int i = blockIdx.x * 256 + threadIdx.x;
    if (i < N_NODES) g_deg[i] = 0;
}

__global__ __launch_bounds__(256) void k_hist(const int* __restrict__ ei) {
    int e = blockIdx.x * 256 + threadIdx.x;          // grid covers E exactly
    atomicAdd(&g_deg[ei[N_EDGES + e]], 1);
}

__global__ __launch_bounds__(256) void k_scan1() {
    __shared__ int s[256];
    const int tid = threadIdx.x;
    const int base = blockIdx.x * 1024 + tid * 4;
    int d0 = 0, d1 = 0, d2 = 0, d3 = 0;
    if (base + 3 < N_NODES) {
        int4 v = *(const int4*)&g_deg[base];
        d0 = v.x; d1 = v.y; d2 = v.z; d3 = v.w;
    } else {
        if (base + 0 < N_NODES) d0 = g_deg[base + 0];
        if (base + 1 < N_NODES) d1 = g_deg[base + 1];
        if (base + 2 < N_NODES) d2 = g_deg[base + 2];
        if (base + 3 < N_NODES) d3 = g_deg[base + 3];
    }
    int s0 = d0, s1 = s0 + d1, s2 = s1 + d2, s3 = s2 + d3;
    s[tid] = s3;
    __syncthreads();
    #pragma unroll
    for (int off = 1; off < 256; off <<= 1) {
        int v = (tid >= off) ? s[tid - off] : 0;
        __syncthreads();
        s[tid] += v;
        __syncthreads();
    }
    int excl = s[tid] - s3;
    if (base + 0 < N_NODES) g_row[base + 0] = excl;
    if (base + 1 < N_NODES) g_row[base + 1] = excl + s0;
    if (base + 2 < N_NODES) g_row[base + 2] = excl + s1;
    if (base + 3 < N_NODES) g_row[base + 3] = excl + s2;
    if (tid == 255) g_bsum[blockIdx.x] = s[255];
}

__global__ __launch_bounds__(256) void k_scan2() {
    __shared__ int s[256];
    const int tid = threadIdx.x;
    int v = (tid < NBLK_SCAN) ? g_bsum[tid] : 0;
    s[tid] = v;
    __syncthreads();
    #pragma unroll
    for (int off = 1; off < 256; off <<= 1) {
        int u = (tid >= off) ? s[tid - off] : 0;
        __syncthreads();
        s[tid] += u;
        __syncthreads();
    }
    if (tid < NBLK_SCAN) g_boff[tid] = s[tid] - v;
}

__global__ __launch_bounds__(256) void k_scan3() {
    int i = blockIdx.x * 256 + threadIdx.x;
    if (i >= N_NODES) return;
    int start = g_row[i] + g_boff[i >> 10];
    g_row[i] = start;
    g_cur[i] = start;
    g_dinv[i] = rsqrtf((float)g_deg[i] + 1.0f);
}

__global__ __launch_bounds__(256) void k_build(const int* __restrict__ ei) {
    int e = blockIdx.x * 256 + threadIdx.x;          // grid covers E exactly
    int src = ei[e];
    int dst = ei[N_EDGES + e];
    int pos = atomicAdd(&g_cur[dst], 1);
    g_col[pos] = src;
}

// ---------------- one-time weight transpose+convert to fp16 ----------------
__global__ __launch_bounds__(256) void k_wt(const float* __restrict__ W1,
                                            const float* __restrict__ W2) {
    int i = blockIdx.x * 256 + threadIdx.x;            // 144*256 = 36864
    if (i < H1 * IN_DIM) {
        int n = i >> 7, k = i & 127;
        g_w1h[i] = __float2half_rn(W1[k * H1 + n]);
    } else {
        int j = i - H1 * IN_DIM;                       // < 4096
        int n = j >> 8, k = j & 255;
        g_w2h[j] = __float2half_rn(W2[k * HID + n]);
    }
}

// ---------------- fused MLP: h = lrelu(lrelu(x@W1+b1)@W2+b2) ---------------
#define SX_H   0
#define SW1_H  34816
#define SW2_H  69632
#define SRED_B 147712
#define SB1_B  168192
#define SB2_B  169216
#define SMEM_MLP 169280

__global__ __launch_bounds__(512, 1) void k_mlp(const float* __restrict__ x,
                                                const float* __restrict__ b1v,
                                                const float* __restrict__ b2v) {
    extern __shared__ char smem[];
    __half* s_x  = (__half*)smem + SX_H;
    __half* s_w1 = (__half*)smem + SW1_H;
    __half* s_w2 = (__half*)smem + SW2_H;
    float*  s_red = (float*)(smem + SRED_B);
    float*  s_b1  = (float*)(smem + SB1_B);
    float*  s_b2  = (float*)(smem + SB2_B);

    const int tid = threadIdx.x, wid = tid >> 5, lane = tid & 31;
    const int qrow = lane >> 2, qcol = lane & 3;
    const int mrow = (wid & 7) * 32;
    const int wcol = (wid >> 3) * 64;
    const int rowbase = blockIdx.x * 256;

    if (tid < 256) s_b1[tid] = b1v[tid];
    if (tid < 16)  s_b2[tid] = b2v[tid];

    for (int i = tid; i < 256 * 32; i += 512) {
        int r = i >> 5, k4 = (i & 31) * 4;
        float4 v = make_float4(0.f, 0.f, 0.f, 0.f);
        int gr = rowbase + r;
        if (gr < N_NODES) v = *(const float4*)(x + (size_t)gr * IN_DIM + k4);
        __half2 h0 = __floats2half2_rn(v.x, v.y);
        __half2 h1 = __floats2half2_rn(v.z, v.w);
        uint2 u = make_uint2(*(uint32_t*)&h0, *(uint32_t*)&h1);
        *(uint2*)&s_x[r * 136 + k4] = u;
    }
    for (int i = tid; i < 256 * 32; i += 512) {
        int n = i >> 5, k4 = (i & 31) * 4;
        uint2 u = *(const uint2*)&g_w1h[n * IN_DIM + k4];
        *(uint2*)&s_w1[n * 136 + k4] = u;
    }
    for (int i = tid; i < 16 * 64; i += 512) {
        int n = i >> 6, k4 = (i & 63) * 4;
        uint2 u = *(const uint2*)&g_w2h[n * H1 + k4];
        *(uint2*)&s_w2[n * 264 + k4] = u;
    }
    __syncthreads();

    float d[2][2][4];
    #pragma unroll
    for (int mi = 0; mi < 2; ++mi)
        #pragma unroll
        for (int nt = 0; nt < 2; ++nt)
            #pragma unroll
            for (int q = 0; q < 4; ++q) d[mi][nt][q] = 0.f;

    #pragma unroll 1
    for (int nh = 0; nh < 2; ++nh) {
        float c[2][8][4];
        #pragma unroll
        for (int mi = 0; mi < 2; ++mi)
            #pragma unroll
            for (int ni = 0; ni < 8; ++ni)
                #pragma unroll
                for (int q = 0; q < 4; ++q) c[mi][ni][q] = 0.f;

        #pragma unroll 2
        for (int ks = 0; ks < 8; ++ks) {
            const int kk = ks * 16;
            uint32_t a[2][4];
            #pragma unroll
            for (int mi = 0; mi < 2; ++mi) {
                const __half* p = &s_x[(mrow + mi * 16 + qrow) * 136 + kk + qcol * 2];
                a[mi][0] = *(const uint32_t*)p;
                a[mi][1] = *(const uint32_t*)(p + 8 * 136);
                a[mi][2] = *(const uint32_t*)(p + 8);
                a[mi][3] = *(const uint32_t*)(p + 8 * 136 + 8);
            }
            uint32_t b[8][2];
            #pragma unroll
            for (int ni = 0; ni < 8; ++ni) {
                const __half* p = &s_w1[(nh * 128 + wcol + ni * 8 + qrow) * 136 + kk + qcol * 2];
                b[ni][0] = *(const uint32_t*)p;
                b[ni][1] = *(const uint32_t*)(p + 8);
            }
            #pragma unroll
            for (int mi = 0; mi < 2; ++mi)
                #pragma unroll
                for (int ni = 0; ni < 8; ++ni)
                    mma_f16(c[mi][ni], a[mi], b[ni]);
        }

        #pragma unroll
        for (int mi = 0; mi < 2; ++mi) {
            uint32_t ah[8][2];
            #pragma unroll
            for (int ni = 0; ni < 8; ++ni) {
                int col0 = nh * 128 + wcol + ni * 8 + qcol * 2;
                float bb0 = s_b1[col0], bb1 = s_b1[col0 + 1];
                float f0 = lrelu(c[mi][ni][0] + bb0);
                float f1 = lrelu(c[mi][ni][1] + bb1);
                float f2 = lrelu(c[mi][ni][2] + bb0);
                float f3 = lrelu(c[mi][ni][3] + bb1);
                __half2 h01 = __floats2half2_rn(f0, f1);
                __half2 h23 = __floats2half2_rn(f2, f3);
                ah[ni][0] = *(uint32_t*)&h01;
                ah[ni][1] = *(uint32_t*)&h23;
            }
            #pragma unroll
            for (int j = 0; j < 4; ++j) {
                uint32_t afr[4] = {ah[2*j][0], ah[2*j][1], ah[2*j+1][0], ah[2*j+1][1]};
                int kg = nh * 128 + wcol + j * 16;
                #pragma unroll
                for (int nt = 0; nt < 2; ++nt) {
                    const __half* p = &s_w2[(nt * 8 + qrow) * 264 + kg + qcol * 2];
                    uint32_t bb[2] = {*(const uint32_t*)p, *(const uint32_t*)(p + 8)};
                    mma_f16(d[mi][nt], afr, bb);
                }
            }
        }
    }

    if (wid >= 8) {
        #pragma unroll
        for (int mi = 0; mi < 2; ++mi)
            #pragma unroll
            for (int nt = 0; nt < 2; ++nt)
                #pragma unroll
                for (int q = 0; q < 4; ++q) {
                    int rl = mrow + mi * 16 + qrow + (q >> 1) * 8;
                    int col = nt * 8 + qcol * 2 + (q & 1);
                    s_red[rl * 20 + col] = d[mi][nt][q];
                }
    }
    __syncthreads();
    if (wid < 8) {
        #pragma unroll
        for (int mi = 0; mi < 2; ++mi)
            #pragma unroll
            for (int nt = 0; nt < 2; ++nt)
                #pragma unroll
                for (int q = 0; q < 4; ++q) {
                    int rl = mrow + mi * 16 + qrow + (q >> 1) * 8;
                    int col = nt * 8 + qcol * 2 + (q & 1);
                    float v = d[mi][nt][q] + s_red[rl * 20 + col];
                    s_red[rl * 20 + col] = lrelu(v + s_b2[col]);
                }
    }
    __syncthreads();
    {
        int r = tid >> 1, part = tid & 1;
        int gr = rowbase + r;
        if (gr < N_NODES) {
            float4 v0 = *(float4*)&s_red[r * 20 + part * 8];
            float4 v1 = *(float4*)&s_red[r * 20 + part * 8 + 4];
            *(float4*)(g_h + (size_t)gr * 16 + part * 8)     = v0;
            *(float4*)(g_h + (size_t)gr * 16 + part * 8 + 4) = v1;
        }
    }
}

// ---------------- t = fp16( dinv * (h @ W) ) -------------------------------
__global__ __launch_bounds__(256) void k_t(const float* __restrict__ W) {
    __shared__ float Ws[256];
    Ws[threadIdx.x] = W[threadIdx.x];
    __syncthreads();
    int i = blockIdx.x * 256 + threadIdx.x;
    if (i >= N_NODES) return;

    const float4* hp = (const float4*)(g_h + (size_t)i * 16);
    float4 h0 = hp[0], h1 = hp[1], h2 = hp[2], h3 = hp[3];
    float hr[16] = {h0.x, h0.y, h0.z, h0.w, h1.x, h1.y, h1.z, h1.w,
                    h2.x, h2.y, h2.z, h2.w, h3.x, h3.y, h3.z, h3.w};
    float acc[16];
    #pragma unroll
    for (int j = 0; j < 16; ++j) acc[j] = 0.f;
    #pragma unroll
    for (int k = 0; k < 16; ++k) {
        float hv = hr[k];
        #pragma unroll
        for (int j = 0; j < 16; ++j) acc[j] += hv * Ws[k * 16 + j];
    }
    float dv = g_dinv[i];
    uint32_t uu[8];
    #pragma unroll
    for (int k = 0; k < 8; ++k) {
        __half2 hh = __floats2half2_rn(acc[2 * k] * dv, acc[2 * k + 1] * dv);
        uu[k] = *(uint32_t*)&hh;
    }
    uint4* tp = (uint4*)(g_t + (size_t)i * 16);
    tp[0] = make_uint4(uu[0], uu[1], uu[2], uu[3]);
    tp[1] = make_uint4(uu[4], uu[5], uu[6], uu[7]);
}

// ---------------- CSR gather: h = lrelu(dinv*(t_self + sum t[src]) + b) ----
// 2 threads per node, each owns 8 channels (16B of the 32B fp16 row).
__global__ __launch_bounds__(256) void k_gather(const float* __restrict__ b) {
    __shared__ float sb[16];
    if (threadIdx.x < 16) sb[threadIdx.x] = b[threadIdx.x];
    __syncthreads();
    int gid = blockIdx.x * 256 + threadIdx.x;
    int node = gid >> 1, q = gid & 1;
    if (node >= N_NODES) return;

    const int start = g_row[node];
    const int deg   = g_deg[node];
    const __half* tq = g_t + q * 8;

    float acc[8];
    {   // self loop
        uint4 v = *(const uint4*)(tq + (size_t)node * 16);
        const __half2* hp = (const __half2*)&v;
        #pragma unroll
        for (int k = 0; k < 4; ++k) {
            float2 f = __half22float2(hp[k]);
            acc[2 * k] = f.x; acc[2 * k + 1] = f.y;
        }
    }
    int j = start, end = start + deg;
    for (; j + 1 < end; j += 2) {
        int s0 = __ldg(&g_col[j]);
        int s1 = __ldg(&g_col[j + 1]);
        uint4 v0 = *(const uint4*)(tq + (size_t)s0 * 16);
        uint4 v1 = *(const uint4*)(tq + (size_t)s1 * 16);
        const __half2* p0 = (const __half2*)&v0;
        const __half2* p1 = (const __half2*)&v1;
        #pragma unroll
        for (int k = 0; k < 4; ++k) {
            float2 f0 = __half22float2(p0[k]);
            float2 f1 = __half22float2(p1[k]);
            acc[2 * k]     += f0.x + f1.x;
            acc[2 * k + 1] += f0.y + f1.y;
        }
    }
    if (j < end) {
        int s0 = __ldg(&g_col[j]);
        uint4 v0 = *(const uint4*)(tq + (size_t)s0 * 16);
        const __half2* p0 = (const __half2*)&v0;
        #pragma unroll
        for (int k = 0; k < 4; ++k) {
            float2 f0 = __half22float2(p0[k]);
            acc[2 * k] += f0.x; acc[2 * k + 1] += f0.y;
        }
    }
    float dv = g_dinv[node];
    float4 r0, r1;
    r0.x = lrelu(dv * acc[0] + sb[q * 8 + 0]);
    r0.y = lrelu(dv * acc[1] + sb[q * 8 + 1]);
    r0.z = lrelu(dv * acc[2] + sb[q * 8 + 2]);
    r0.w = lrelu(dv * acc[3] + sb[q * 8 + 3]);
    r1.x = lrelu(dv * acc[4] + sb[q * 8 + 4]);
    r1.y = lrelu(dv * acc[5] + sb[q * 8 + 5]);
    r1.z = lrelu(dv * acc[6] + sb[q * 8 + 6]);
    r1.w = lrelu(dv * acc[7] + sb[q * 8 + 7]);
    float* hp = g_h + (size_t)node * 16 + q * 8;
    *(float4*)hp = r0;
    *(float4*)(hp + 4) = r1;
}

// ---------------- head -----------------------------------------------------
__global__ __launch_bounds__(256) void k_out(const float* __restrict__ pw,
                                             const float* __restrict__ pb,
                                             float* __restrict__ out) {
    int i = blockIdx.x * 256 + threadIdx.x;
    if (i >= N_NODES) return;
    float bs = pb[0] + pb[1];
    const float4* hp = (const float4*)(g_h + (size_t)i * 16);
    float4 h0 = hp[0], h1 = hp[1], h2 = hp[2], h3 = hp[3];
    float hr[16] = {h0.x, h0.y, h0.z, h0.w, h1.x, h1.y, h1.z, h1.w,
                    h2.x, h2.y, h2.z, h2.w, h3.x, h3.y, h3.z, h3.w};
    float s = bs;
    #pragma unroll
    for (int k = 0; k < 16; ++k) s += hr[k] * (pw[k * 2] + pw[k * 2 + 1]);
    out[i] = s;
    float4* op = (float4*)(out + N_NODES + (size_t)i * 16);
    op[0] = h0; op[1] = h1; op[2] = h2; op[3] = h3;
}

// ---------------------------------------------------------------------------
extern "C" void kernel_launch(void* const* d_in, const int* in_sizes, int n_in,
                              void* d_out, int out_size) {
    const float* x   = (const float*)d_in[0];
    const float* W1  = (const float*)d_in[1];
    const float* b1  = (const float*)d_in[2];
    const float* W2  = (const float*)d_in[3];
    const float* b2  = (const float*)d_in[4];
    const float* cw0 = (const float*)d_in[5];
    const float* cb0 = (const float*)d_in[6];
    const float* cw1 = (const float*)d_in[7];
    const float* cb1 = (const float*)d_in[8];
    const float* pw  = (const float*)d_in[9];
    const float* pb  = (const float*)d_in[10];
    const int*   ei  = (const int*)d_in[11];
    float* out = (float*)d_out;

    static cudaStream_t s1;
    static cudaEvent_t ev_fork, ev_join;
    static int inited = 0;
    if (!inited) {
        cudaFuncSetAttribute(k_mlp, cudaFuncAttributeMaxDynamicSharedMemorySize, SMEM_MLP);
        cudaStreamCreateWithFlags(&s1, cudaStreamNonBlocking);
        cudaEventCreateWithFlags(&ev_fork, cudaEventDisableTiming);
        cudaEventCreateWithFlags(&ev_join, cudaEventDisableTiming);
        inited = 1;
    }

    // fork: CSR build on side stream, overlapped with weight prep + MLP
    cudaEventRecord(ev_fork, 0);
    cudaStreamWaitEvent(s1, ev_fork, 0);

    k_zero<<<782, 256, 0, s1>>>();
    k_hist<<<N_EDGES / 256, 256, 0, s1>>>(ei);
    k_scan1<<<NBLK_SCAN, 256, 0, s1>>>();
    k_scan2<<<1, 256, 0, s1>>>();
    k_scan3<<<782, 256, 0, s1>>>();
    k_build<<<N_EDGES / 256, 256, 0, s1>>>(ei);
    cudaEventRecord(ev_join, s1);

    // main stream: MLP (no CSR dependency)
    k_wt<<<144, 256>>>(W1, W2);
    k_mlp<<<782, 512, SMEM_MLP>>>(x, b1, b2);

    // join: k_t needs g_dinv (CSR chain)
    cudaStreamWaitEvent(0, ev_join, 0);

    // conv layer 0
    k_t<<<782, 256>>>(cw0);
    k_gather<<<(2 * N_NODES + 255) / 256, 256>>>(cb0);

    // conv layer 1
    k_t<<<782, 256>>>(cw1);
    k_gather<<<(2 * N_NODES + 255) / 256, 256>>>(cb1);

    k_out<<<782, 256>>>(pw, pb, out);
}

// round 7
// speedup vs baseline: 2.2536x; 1.0621x over previous
#include <cuda_runtime.h>
#include <cuda_fp16.h>
#include <cstdint>

#define N_NODES 200000
#define N_EDGES 6400000
#define IN_DIM  128
#define H1      256
#define HID     16
#define NEG     0.01f
#define NBLK_SCAN 196   // ceil(200000/1024)

// ---------------- scratch (device globals; no runtime allocation) ----------
__device__ __align__(16) float  g_dinv[N_NODES];
__device__ __align__(16) float  g_h  [N_NODES * HID];   // MLP output (fp32)
__device__ __align__(16) __half g_u0 [N_NODES * HID];   // dinv*h, layer-0 messages
__device__ __align__(16) __half g_u1 [N_NODES * HID];   // layer-1 messages
__device__ __align__(16) __half g_w1h[H1 * IN_DIM];     // [256][128] = W1^T fp16
__device__ __align__(16) __half g_w2h[HID * H1];        // [16][256]  = W2^T fp16
__device__ __align__(16) int    g_deg[N_NODES];
__device__ __align__(16) int    g_row[N_NODES];         // CSR row starts (by dst)
__device__ __align__(16) int    g_cur[N_NODES];         // build cursors
__device__ __align__(16) int    g_col[N_EDGES];         // CSR: src per incoming edge
__device__              int     g_bsum[NBLK_SCAN];
__device__              int     g_boff[NBLK_SCAN];

__device__ __forceinline__ float lrelu(float v) { return v >= 0.f ? v : NEG * v; }

__device__ __forceinline__ void mma_f16(float* c, const uint32_t* a, const uint32_t* b) {
    asm volatile("mma.sync.aligned.m16n8k16.row.col.f32.f16.f16.f32 "
                 "{%0,%1,%2,%3}, {%4,%5,%6,%7}, {%8,%9}, {%0,%1,%2,%3};"
                 : "+f"(c[0]), "+f"(c[1]), "+f"(c[2]), "+f"(c[3])
                 : "r"(a[0]), "r"(a[1]), "r"(a[2]), "r"(a[3]), "r"(b[0]), "r"(b[1]));
}

// ---------------- CSR build: histogram, scan, bucket scatter ---------------
__global__ __launch_bounds__(256) void k_zero() {
    int i = blockIdx.x * 256 + threadIdx.x;
    if (i < N_NODES) g_deg[i] = 0;
}

__global__ __launch_bounds__(256) void k_hist(const int* __restrict__ ei) {
    int e = blockIdx.x * 256 + threadIdx.x;          // grid covers E exactly
    atomicAdd(&g_deg[ei[N_EDGES + e]], 1);
}

__global__ __launch_bounds__(256) void k_scan1() {
    __shared__ int s[256];
    const int tid = threadIdx.x;
    const int base = blockIdx.x * 1024 + tid * 4;
    int d0 = 0, d1 = 0, d2 = 0, d3 = 0;
    if (base + 3 < N_NODES) {
        int4 v = *(const int4*)&g_deg[base];
        d0 = v.x; d1 = v.y; d2 = v.z; d3 = v.w;
    } else {
        if (base + 0 < N_NODES) d0 = g_deg[base + 0];
        if (base + 1 < N_NODES) d1 = g_deg[base + 1];
        if (base + 2 < N_NODES) d2 = g_deg[base + 2];
        if (base + 3 < N_NODES) d3 = g_deg[base + 3];
    }
    int s0 = d0, s1 = s0 + d1, s2 = s1 + d2, s3 = s2 + d3;
    s[tid] = s3;
    __syncthreads();
    #pragma unroll
    for (int off = 1; off < 256; off <<= 1) {
        int v = (tid >= off) ? s[tid - off] : 0;
        __syncthreads();
        s[tid] += v;
        __syncthreads();
    }
    int excl = s[tid] - s3;
    if (base + 0 < N_NODES) g_row[base + 0] = excl;
    if (base + 1 < N_NODES) g_row[base + 1] = excl + s0;
    if (base + 2 < N_NODES) g_row[base + 2] = excl + s1;
    if (base + 3 < N_NODES) g_row[base + 3] = excl + s2;
    if (tid == 255) g_bsum[blockIdx.x] = s[255];
}

__global__ __launch_bounds__(256) void k_scan2() {
    __shared__ int s[256];
    const int tid = threadIdx.x;
    int v = (tid < NBLK_SCAN) ? g_bsum[tid] : 0;
    s[tid] = v;
    __syncthreads();
    #pragma unroll
    for (int off = 1; off < 256; off <<= 1) {
        int u = (tid >= off) ? s[tid - off] : 0;
        __syncthreads();
        s[tid] += u;
        __syncthreads();
    }
    if (tid < NBLK_SCAN) g_boff[tid] = s[tid] - v;
}

__global__ __launch_bounds__(256) void k_scan3() {
    int i = blockIdx.x * 256 + threadIdx.x;
    if (i >= N_NODES) return;
    int start = g_row[i] + g_boff[i >> 10];
    g_row[i] = start;
    g_cur[i] = start;
    g_dinv[i] = rsqrtf((float)g_deg[i] + 1.0f);
}

__global__ __launch_bounds__(256) void k_build(const int* __restrict__ ei) {
    int e = blockIdx.x * 256 + threadIdx.x;          // grid covers E exactly
    int src = ei[e];
    int dst = ei[N_EDGES + e];
    int pos = atomicAdd(&g_cur[dst], 1);
    g_col[pos] = src;
}

// ---------------- one-time weight transpose+convert to fp16 ----------------
__global__ __launch_bounds__(256) void k_wt(const float* __restrict__ W1,
                                            const float* __restrict__ W2) {
    int i = blockIdx.x * 256 + threadIdx.x;            // 144*256 = 36864
    if (i < H1 * IN_DIM) {
        int n = i >> 7, k = i & 127;
        g_w1h[i] = __float2half_rn(W1[k * H1 + n]);
    } else {
        int j = i - H1 * IN_DIM;                       // < 4096
        int n = j >> 8, k = j & 255;
        g_w2h[j] = __float2half_rn(W2[k * HID + n]);
    }
}

// ---------------- fused MLP: h = lrelu(lrelu(x@W1+b1)@W2+b2) ---------------
#define SX_H   0
#define SW1_H  34816
#define SW2_H  69632
#define SRED_B 147712
#define SB1_B  168192
#define SB2_B  169216
#define SMEM_MLP 169280

__global__ __launch_bounds__(512, 1) void k_mlp(const float* __restrict__ x,
                                                const float* __restrict__ b1v,
                                                const float* __restrict__ b2v) {
    extern __shared__ char smem[];
    __half* s_x  = (__half*)smem + SX_H;
    __half* s_w1 = (__half*)smem + SW1_H;
    __half* s_w2 = (__half*)smem + SW2_H;
    float*  s_red = (float*)(smem + SRED_B);
    float*  s_b1  = (float*)(smem + SB1_B);
    float*  s_b2  = (float*)(smem + SB2_B);

    const int tid = threadIdx.x, wid = tid >> 5, lane = tid & 31;
    const int qrow = lane >> 2, qcol = lane & 3;
    const int mrow = (wid & 7) * 32;
    const int wcol = (wid >> 3) * 64;
    const int rowbase = blockIdx.x * 256;

    if (tid < 256) s_b1[tid] = b1v[tid];
    if (tid < 16)  s_b2[tid] = b2v[tid];

    for (int i = tid; i < 256 * 32; i += 512) {
        int r = i >> 5, k4 = (i & 31) * 4;
        float4 v = make_float4(0.f, 0.f, 0.f, 0.f);
        int gr = rowbase + r;
        if (gr < N_NODES) v = *(const float4*)(x + (size_t)gr * IN_DIM + k4);
        __half2 h0 = __floats2half2_rn(v.x, v.y);
        __half2 h1 = __floats2half2_rn(v.z, v.w);
        uint2 u = make_uint2(*(uint32_t*)&h0, *(uint32_t*)&h1);
        *(uint2*)&s_x[r * 136 + k4] = u;
    }
    for (int i = tid; i < 256 * 32; i += 512) {
        int n = i >> 5, k4 = (i & 31) * 4;
        uint2 u = *(const uint2*)&g_w1h[n * IN_DIM + k4];
        *(uint2*)&s_w1[n * 136 + k4] = u;
    }
    for (int i = tid; i < 16 * 64; i += 512) {
        int n = i >> 6, k4 = (i & 63) * 4;
        uint2 u = *(const uint2*)&g_w2h[n * H1 + k4];
        *(uint2*)&s_w2[n * 264 + k4] = u;
    }
    __syncthreads();

    float d[2][2][4];
    #pragma unroll
    for (int mi = 0; mi < 2; ++mi)
        #pragma unroll
        for (int nt = 0; nt < 2; ++nt)
            #pragma unroll
            for (int q = 0; q < 4; ++q) d[mi][nt][q] = 0.f;

    #pragma unroll 1
    for (int nh = 0; nh < 2; ++nh) {
        float c[2][8][4];
        #pragma unroll
        for (int mi = 0; mi < 2; ++mi)
            #pragma unroll
            for (int ni = 0; ni < 8; ++ni)
                #pragma unroll
                for (int q = 0; q < 4; ++q) c[mi][ni][q] = 0.f;

        #pragma unroll 2
        for (int ks = 0; ks < 8; ++ks) {
            const int kk = ks * 16;
            uint32_t a[2][4];
            #pragma unroll
            for (int mi = 0; mi < 2; ++mi) {
                const __half* p = &s_x[(mrow + mi * 16 + qrow) * 136 + kk + qcol * 2];
                a[mi][0] = *(const uint32_t*)p;
                a[mi][1] = *(const uint32_t*)(p + 8 * 136);
                a[mi][2] = *(const uint32_t*)(p + 8);
                a[mi][3] = *(const uint32_t*)(p + 8 * 136 + 8);
            }
            uint32_t b[8][2];
            #pragma unroll
            for (int ni = 0; ni < 8; ++ni) {
                const __half* p = &s_w1[(nh * 128 + wcol + ni * 8 + qrow) * 136 + kk + qcol * 2];
                b[ni][0] = *(const uint32_t*)p;
                b[ni][1] = *(const uint32_t*)(p + 8);
            }
            #pragma unroll
            for (int mi = 0; mi < 2; ++mi)
                #pragma unroll
                for (int ni = 0; ni < 8; ++ni)
                    mma_f16(c[mi][ni], a[mi], b[ni]);
        }

        #pragma unroll
        for (int mi = 0; mi < 2; ++mi) {
            uint32_t ah[8][2];
            #pragma unroll
            for (int ni = 0; ni < 8; ++ni) {
                int col0 = nh * 128 + wcol + ni * 8 + qcol * 2;
                float bb0 = s_b1[col0], bb1 = s_b1[col0 + 1];
                float f0 = lrelu(c[mi][ni][0] + bb0);
                float f1 = lrelu(c[mi][ni][1] + bb1);
                float f2 = lrelu(c[mi][ni][2] + bb0);
                float f3 = lrelu(c[mi][ni][3] + bb1);
                __half2 h01 = __floats2half2_rn(f0, f1);
                __half2 h23 = __floats2half2_rn(f2, f3);
                ah[ni][0] = *(uint32_t*)&h01;
                ah[ni][1] = *(uint32_t*)&h23;
            }
            #pragma unroll
            for (int j = 0; j < 4; ++j) {
                uint32_t afr[4] = {ah[2*j][0], ah[2*j][1], ah[2*j+1][0], ah[2*j+1][1]};
                int kg = nh * 128 + wcol + j * 16;
                #pragma unroll
                for (int nt = 0; nt < 2; ++nt) {
                    const __half* p = &s_w2[(nt * 8 + qrow) * 264 + kg + qcol * 2];
                    uint32_t bb[2] = {*(const uint32_t*)p, *(const uint32_t*)(p + 8)};
                    mma_f16(d[mi][nt], afr, bb);
                }
            }
        }
    }

    if (wid >= 8) {
        #pragma unroll
        for (int mi = 0; mi < 2; ++mi)
            #pragma unroll
            for (int nt = 0; nt < 2; ++nt)
                #pragma unroll
                for (int q = 0; q < 4; ++q) {
                    int rl = mrow + mi * 16 + qrow + (q >> 1) * 8;
                    int col = nt * 8 + qcol * 2 + (q & 1);
                    s_red[rl * 20 + col] = d[mi][nt][q];
                }
    }
    __syncthreads();
    if (wid < 8) {
        #pragma unroll
        for (int mi = 0; mi < 2; ++mi)
            #pragma unroll
            for (int nt = 0; nt < 2; ++nt)
                #pragma unroll
                for (int q = 0; q < 4; ++q) {
                    int rl = mrow + mi * 16 + qrow + (q >> 1) * 8;
                    int col = nt * 8 + qcol * 2 + (q & 1);
                    float v = d[mi][nt][q] + s_red[rl * 20 + col];
                    s_red[rl * 20 + col] = lrelu(v + s_b2[col]);
                }
    }
    __syncthreads();
    {
        int r = tid >> 1, part = tid & 1;
        int gr = rowbase + r;
        if (gr < N_NODES) {
            float4 v0 = *(float4*)&s_red[r * 20 + part * 8];
            float4 v1 = *(float4*)&s_red[r * 20 + part * 8 + 4];
            *(float4*)(g_h + (size_t)gr * 16 + part * 8)     = v0;
            *(float4*)(g_h + (size_t)gr * 16 + part * 8 + 4) = v1;
        }
    }
}

// ---------------- u0 = fp16(dinv * h) --------------------------------------
__global__ __launch_bounds__(256) void k_u0() {
    int gid = blockIdx.x * 256 + threadIdx.x;
    int node = gid >> 1, q = gid & 1;
    if (node >= N_NODES) return;
    float dv = g_dinv[node];
    const float* hp = g_h + (size_t)node * 16 + q * 8;
    float4 a = *(const float4*)hp;
    float4 b = *(const float4*)(hp + 4);
    __half2 h0 = __floats2half2_rn(a.x * dv, a.y * dv);
    __half2 h1 = __floats2half2_rn(a.z * dv, a.w * dv);
    __half2 h2 = __floats2half2_rn(b.x * dv, b.y * dv);
    __half2 h3 = __floats2half2_rn(b.z * dv, b.w * dv);
    *(uint4*)(g_u0 + (size_t)node * 16 + q * 8) =
        make_uint4(*(uint32_t*)&h0, *(uint32_t*)&h1, *(uint32_t*)&h2, *(uint32_t*)&h3);
}

// ---------------- aggregate helper: 8 channels per thread ------------------
__device__ __forceinline__ void agg8(const __half* __restrict__ uin, int node, int q,
                                     float* acc) {
    const __half* uq = uin + q * 8;
    {   // self loop
        uint4 v = *(const uint4*)(uq + (size_t)node * 16);
        const __half2* hp = (const __half2*)&v;
        #pragma unroll
        for (int k = 0; k < 4; ++k) {
            float2 f = __half22float2(hp[k]);
            acc[2 * k] = f.x; acc[2 * k + 1] = f.y;
        }
    }
    int j = g_row[node], end = j + g_deg[node];
    for (; j + 3 < end; j += 4) {
        int s0 = __ldg(&g_col[j + 0]);
        int s1 = __ldg(&g_col[j + 1]);
        int s2 = __ldg(&g_col[j + 2]);
        int s3 = __ldg(&g_col[j + 3]);
        uint4 v0 = *(const uint4*)(uq + (size_t)s0 * 16);
        uint4 v1 = *(const uint4*)(uq + (size_t)s1 * 16);
        uint4 v2 = *(const uint4*)(uq + (size_t)s2 * 16);
        uint4 v3 = *(const uint4*)(uq + (size_t)s3 * 16);
        const __half2* p0 = (const __half2*)&v0;
        const __half2* p1 = (const __half2*)&v1;
        const __half2* p2 = (const __half2*)&v2;
        const __half2* p3 = (const __half2*)&v3;
        #pragma unroll
        for (int k = 0; k < 4; ++k) {
            float2 f0 = __half22float2(p0[k]);
            float2 f1 = __half22float2(p1[k]);
            float2 f2 = __half22float2(p2[k]);
            float2 f3 = __half22float2(p3[k]);
            acc[2 * k]     += (f0.x + f1.x) + (f2.x + f3.x);
            acc[2 * k + 1] += (f0.y + f1.y) + (f2.y + f3.y);
        }
    }
    for (; j < end; ++j) {
        int s0 = __ldg(&g_col[j]);
        uint4 v0 = *(const uint4*)(uq + (size_t)s0 * 16);
        const __half2* p0 = (const __half2*)&v0;
        #pragma unroll
        for (int k = 0; k < 4; ++k) {
            float2 f0 = __half22float2(p0[k]);
            acc[2 * k] += f0.x; acc[2 * k + 1] += f0.y;
        }
    }
}

// exchange 8 partner channels and assemble full 16-vector
__device__ __forceinline__ void exch16(const float* acc, int q, float* pre) {
    unsigned mask = __activemask();
    float oth[8];
    #pragma unroll
    for (int k = 0; k < 8; ++k) oth[k] = __shfl_xor_sync(mask, acc[k], 1);
    #pragma unroll
    for (int k = 0; k < 8; ++k) {
        pre[k]     = q ? oth[k] : acc[k];
        pre[k + 8] = q ? acc[k] : oth[k];
    }
}

// ---------------- conv layer 0: u1 = dinv*lrelu(dinv*agg(u0) @ W + b) ------
__global__ __launch_bounds__(256) void k_conv0(const float* __restrict__ W,
                                               const float* __restrict__ b) {
    __shared__ float s_w[256];
    __shared__ float s_b[16];
    if (threadIdx.x < 256) s_w[threadIdx.x] = W[threadIdx.x];
    if (threadIdx.x < 16)  s_b[threadIdx.x] = b[threadIdx.x];
    __syncthreads();

    int gid = blockIdx.x * 256 + threadIdx.x;
    int node = gid >> 1, q = gid & 1;
    if (node >= N_NODES) return;

    float acc[8];
    agg8(g_u0, node, q, acc);
    float dv = g_dinv[node];
    #pragma unroll
    for (int k = 0; k < 8; ++k) acc[k] *= dv;

    float pre[16];
    exch16(acc, q, pre);

    // matvec: o[j] = sum_k pre[k]*W[k][j] for j in [q*8, q*8+8)
    float o[8];
    #pragma unroll
    for (int jj = 0; jj < 8; ++jj) o[jj] = s_b[q * 8 + jj];
    #pragma unroll
    for (int k = 0; k < 16; ++k) {
        float p = pre[k];
        float4 w0 = *(const float4*)&s_w[k * 16 + q * 8];
        float4 w1 = *(const float4*)&s_w[k * 16 + q * 8 + 4];
        o[0] += p * w0.x; o[1] += p * w0.y; o[2] += p * w0.z; o[3] += p * w0.w;
        o[4] += p * w1.x; o[5] += p * w1.y; o[6] += p * w1.z; o[7] += p * w1.w;
    }
    #pragma unroll
    for (int jj = 0; jj < 8; ++jj) o[jj] = lrelu(o[jj]) * dv;   // fold next layer's dinv

    __half2 h0 = __floats2half2_rn(o[0], o[1]);
    __half2 h1 = __floats2half2_rn(o[2], o[3]);
    __half2 h2 = __floats2half2_rn(o[4], o[5]);
    __half2 h3 = __floats2half2_rn(o[6], o[7]);
    *(uint4*)(g_u1 + (size_t)node * 16 + q * 8) =
        make_uint4(*(uint32_t*)&h0, *(uint32_t*)&h1, *(uint32_t*)&h2, *(uint32_t*)&h3);
}

// ---------------- conv layer 1 + head: write h and out to d_out ------------
__global__ __launch_bounds__(256) void k_conv1(const float* __restrict__ W,
                                               const float* __restrict__ b,
                                               const float* __restrict__ pw,
                                               const float* __restrict__ pb,
                                               float* __restrict__ out) {
    __shared__ float s_w[256];
    __shared__ float s_b[16];
    __shared__ float s_pws[16];
    __shared__ float s_pbs;
    if (threadIdx.x < 256) s_w[threadIdx.x] = W[threadIdx.x];
    if (threadIdx.x < 16) {
        s_b[threadIdx.x] = b[threadIdx.x];
        s_pws[threadIdx.x] = pw[threadIdx.x * 2] + pw[threadIdx.x * 2 + 1];
    }
    if (threadIdx.x == 0) s_pbs = pb[0] + pb[1];
    __syncthreads();

    int gid = blockIdx.x * 256 + threadIdx.x;
    int node = gid >> 1, q = gid & 1;
    if (node >= N_NODES) return;

    float acc[8];
    agg8(g_u1, node, q, acc);
    float dv = g_dinv[node];
    #pragma unroll
    for (int k = 0; k < 8; ++k) acc[k] *= dv;

    float pre[16];
    exch16(acc, q, pre);

    float o[8];
    #pragma unroll
    for (int jj = 0; jj < 8; ++jj) o[jj] = s_b[q * 8 + jj];
    #pragma unroll
    for (int k = 0; k < 16; ++k) {
        float p = pre[k];
        float4 w0 = *(const float4*)&s_w[k * 16 + q * 8];
        float4 w1 = *(const float4*)&s_w[k * 16 + q * 8 + 4];
        o[0] += p * w0.x; o[1] += p * w0.y; o[2] += p * w0.z; o[3] += p * w0.w;
        o[4] += p * w1.x; o[5] += p * w1.y; o[6] += p * w1.z; o[7] += p * w1.w;
    }
    #pragma unroll
    for (int jj = 0; jj < 8; ++jj) o[jj] = lrelu(o[jj]);

    // head partial: sum_j o[j] * (pw[j][0]+pw[j][1])
    float s = 0.f;
    #pragma unroll
    for (int jj = 0; jj < 8; ++jj) s += o[jj] * s_pws[q * 8 + jj];
    unsigned mask = __activemask();
    float s_oth = __shfl_xor_sync(mask, s, 1);
    if (q == 0) out[node] = s + s_oth + s_pbs;

    float* hp = out + N_NODES + (size_t)node * 16 + q * 8;
    *(float4*)hp = make_float4(o[0], o[1], o[2], o[3]);
    *(float4*)(hp + 4) = make_float4(o[4], o[5], o[6], o[7]);
}

// ---------------------------------------------------------------------------
extern "C" void kernel_launch(void* const* d_in, const int* in_sizes, int n_in,
                              void* d_out, int out_size) {
    const float* x   = (const float*)d_in[0];
    const float* W1  = (const float*)d_in[1];
    const float* b1  = (const float*)d_in[2];
    const float* W2  = (const float*)d_in[3];
    const float* b2  = (const float*)d_in[4];
    const float* cw0 = (const float*)d_in[5];
    const float* cb0 = (const float*)d_in[6];
    const float* cw1 = (const float*)d_in[7];
    const float* cb1 = (const float*)d_in[8];
    const float* pw  = (const float*)d_in[9];
    const float* pb  = (const float*)d_in[10];
    const int*   ei  = (const int*)d_in[11];
    float* out = (float*)d_out;

    static cudaStream_t s1;
    static cudaEvent_t ev_fork, ev_join;
    static int inited = 0;
    if (!inited) {
        cudaFuncSetAttribute(k_mlp, cudaFuncAttributeMaxDynamicSharedMemorySize, SMEM_MLP);
        cudaStreamCreateWithFlags(&s1, cudaStreamNonBlocking);
        cudaEventCreateWithFlags(&ev_fork, cudaEventDisableTiming);
        cudaEventCreateWithFlags(&ev_join, cudaEventDisableTiming);
        inited = 1;
    }

    const int grid2N = (2 * N_NODES + 255) / 256;

    // fork: CSR build on side stream, overlapped with weight prep + MLP
    cudaEventRecord(ev_fork, 0);
    cudaStreamWaitEvent(s1, ev_fork, 0);

    k_zero<<<782, 256, 0, s1>>>();
    k_hist<<<N_EDGES / 256, 256, 0, s1>>>(ei);
    k_scan1<<<NBLK_SCAN, 256, 0, s1>>>();
    k_scan2<<<1, 256, 0, s1>>>();
    k_scan3<<<782, 256, 0, s1>>>();
    k_build<<<N_EDGES / 256, 256, 0, s1>>>(ei);
    cudaEventRecord(ev_join, s1);

    // main stream: MLP (no CSR dependency)
    k_wt<<<144, 256>>>(W1, W2);
    k_mlp<<<782, 512, SMEM_MLP>>>(x, b1, b2);

    // join: k_u0 needs g_dinv (CSR chain)
    cudaStreamWaitEvent(0, ev_join, 0);

    k_u0<<<grid2N, 256>>>();
    k_conv0<<<grid2N, 256>>>(cw0, cb0);
    k_conv1<<<grid2N, 256>>>(cw1, cb1, pw, pb, out);
}